// round 2
// baseline (speedup 1.0000x reference)
#include <cuda_runtime.h>

#define N_NODES 50000
#define EMBED 128
#define HIDDEN 256
#define N_EDGES 640000
#define LN_EPS 1e-5f

// Scratch (allocation-free rule: __device__ globals)
__device__ float g_h[N_NODES * EMBED];     // layernormed node embeddings
__device__ float g_agg[N_NODES * EMBED];   // segment-sum accumulator

__device__ __forceinline__ float silu_f(float x) {
    return __fdividef(x, 1.0f + __expf(-x));
}

// ---------------------------------------------------------------------------
// Kernel 1: LayerNorm over each node row (warp per row) + zero g_agg
// ---------------------------------------------------------------------------
__global__ void ln_kernel(const float* __restrict__ x,
                          const float* __restrict__ gamma,
                          const float* __restrict__ beta) {
    int warp = (blockIdx.x * blockDim.x + threadIdx.x) >> 5;
    int lane = threadIdx.x & 31;
    if (warp >= N_NODES) return;

    const float4* row = (const float4*)(x + (size_t)warp * EMBED);
    float4 v = row[lane];
    float s  = v.x + v.y + v.z + v.w;
    float ss = v.x * v.x + v.y * v.y + v.z * v.z + v.w * v.w;
    #pragma unroll
    for (int o = 16; o; o >>= 1) {
        s  += __shfl_xor_sync(0xFFFFFFFFu, s,  o);
        ss += __shfl_xor_sync(0xFFFFFFFFu, ss, o);
    }
    const float inv_d = 1.0f / (float)EMBED;
    float mu  = s * inv_d;
    float var = ss * inv_d - mu * mu;
    float inv = rsqrtf(var + LN_EPS);

    float4 g = ((const float4*)gamma)[lane];
    float4 b = ((const float4*)beta)[lane];
    float4 o4;
    o4.x = (v.x - mu) * inv * g.x + b.x;
    o4.y = (v.y - mu) * inv * g.y + b.y;
    o4.z = (v.z - mu) * inv * g.z + b.z;
    o4.w = (v.w - mu) * inv * g.w + b.w;
    ((float4*)(g_h + (size_t)warp * EMBED))[lane] = o4;
    ((float4*)(g_agg + (size_t)warp * EMBED))[lane] = make_float4(0.f, 0.f, 0.f, 0.f);
}

// ---------------------------------------------------------------------------
// Kernel 2: per-edge MLP + scatter-add
//   s = silu(e + h[c] + h[n]); t = silu(s@W1 + b1); theta = t@W2 + b2
//   atomicAdd(agg[c], h[n] * theta)
// 32 edges per CTA, 256 threads, dynamic smem 96.25KB (2 CTAs/SM)
// ---------------------------------------------------------------------------
#define TILE_E 32
#define ETHREADS 256

__global__ __launch_bounds__(ETHREADS)
void edge_kernel(const float* __restrict__ eemb,
                 const int* __restrict__ eidx,
                 const float* __restrict__ W1, const float* __restrict__ b1,
                 const float* __restrict__ W2, const float* __restrict__ b2) {
    extern __shared__ float sm[];
    float* s_s  = sm;                          // [32][128] silu(s)
    float* s_hn = s_s  + TILE_E * EMBED;       // [32][128] h_n
    float* s_t  = s_hn + TILE_E * EMBED;       // [32][256] silu(t)
    float* s_w  = s_t  + TILE_E * HIDDEN;      // [32][256] weight chunk
    int*   s_ci = (int*)(s_w + 32 * HIDDEN);   // [32] center idx
    int*   s_ni = s_ci + TILE_E;               // [32] neighbor idx

    int tid = threadIdx.x;
    int e0 = blockIdx.x * TILE_E;

    if (tid < TILE_E) {
        s_ci[tid] = eidx[e0 + tid];
        s_ni[tid] = eidx[N_EDGES + e0 + tid];
    }
    __syncthreads();

    // ---- Load + fuse: s = silu(e + h_c + h_n), keep h_n ----
    #pragma unroll
    for (int r = 0; r < 4; r++) {
        int v = tid + ETHREADS * r;     // 0..1023 float4 slots
        int e = v >> 5;                 // edge within tile
        int c = v & 31;                 // float4 column
        float4 ee = ((const float4*)(eemb + (size_t)(e0 + e) * EMBED))[c];
        float4 hc = ((const float4*)(g_h + (size_t)s_ci[e] * EMBED))[c];
        float4 hn = ((const float4*)(g_h + (size_t)s_ni[e] * EMBED))[c];
        float4 sv;
        sv.x = silu_f(ee.x + hc.x + hn.x);
        sv.y = silu_f(ee.y + hc.y + hn.y);
        sv.z = silu_f(ee.z + hc.z + hn.z);
        sv.w = silu_f(ee.w + hc.w + hn.w);
        ((float4*)(s_s  + e * EMBED))[c] = sv;
        ((float4*)(s_hn + e * EMBED))[c] = hn;
    }
    __syncthreads();

    // ---- GEMM1: t[32][256] = silu_s[32][128] @ W1[128][256] ----
    // thread -> cols 4*cg..4*cg+3 (cg = tid%64), edges eg*8..eg*8+7 (eg = tid/64)
    {
        int cg = tid & 63;
        int eg = tid >> 6;
        float acc[8][4];
        #pragma unroll
        for (int e = 0; e < 8; e++)
            #pragma unroll
            for (int i = 0; i < 4; i++) acc[e][i] = 0.f;

        for (int kc = 0; kc < EMBED; kc += 32) {
            __syncthreads();   // protect s_w from previous chunk's readers
            #pragma unroll
            for (int r = 0; r < 8; r++) {
                int v = tid + ETHREADS * r;   // 0..2047 float4
                ((float4*)s_w)[v] = ((const float4*)(W1 + (size_t)kc * HIDDEN))[v];
            }
            __syncthreads();
            #pragma unroll
            for (int k = 0; k < 32; k++) {
                float4 w = ((const float4*)(s_w + k * HIDDEN))[cg];
                #pragma unroll
                for (int e = 0; e < 8; e++) {
                    float sv = s_s[(eg * 8 + e) * EMBED + kc + k];   // warp-broadcast
                    acc[e][0] += sv * w.x;
                    acc[e][1] += sv * w.y;
                    acc[e][2] += sv * w.z;
                    acc[e][3] += sv * w.w;
                }
            }
        }
        float4 bb = ((const float4*)b1)[cg];
        #pragma unroll
        for (int e = 0; e < 8; e++) {
            float4 tv;
            tv.x = silu_f(acc[e][0] + bb.x);
            tv.y = silu_f(acc[e][1] + bb.y);
            tv.z = silu_f(acc[e][2] + bb.z);
            tv.w = silu_f(acc[e][3] + bb.w);
            ((float4*)(s_t + (eg * 8 + e) * HIDDEN))[cg] = tv;
        }
    }

    // ---- GEMM2: theta[32][128] = silu_t[32][256] @ W2[256][128] ----
    // thread -> cols 4*cg2..4*cg2+3 (cg2 = tid%32), edges eg2*4..eg2*4+3 (eg2 = tid/32)
    {
        int cg2 = tid & 31;
        int eg2 = tid >> 5;
        float acc[4][4];
        #pragma unroll
        for (int e = 0; e < 4; e++)
            #pragma unroll
            for (int i = 0; i < 4; i++) acc[e][i] = 0.f;

        for (int kc = 0; kc < HIDDEN; kc += 32) {
            __syncthreads();   // s_t stores done (first iter) / s_w readers done
            #pragma unroll
            for (int r = 0; r < 4; r++) {
                int v = tid + ETHREADS * r;   // 0..1023 float4
                ((float4*)s_w)[v] = ((const float4*)(W2 + (size_t)kc * EMBED))[v];
            }
            __syncthreads();
            #pragma unroll
            for (int k = 0; k < 32; k++) {
                float4 w = ((const float4*)(s_w + k * EMBED))[cg2];
                #pragma unroll
                for (int e = 0; e < 4; e++) {
                    float tv = s_t[(eg2 * 4 + e) * HIDDEN + kc + k];  // warp-broadcast
                    acc[e][0] += tv * w.x;
                    acc[e][1] += tv * w.y;
                    acc[e][2] += tv * w.z;
                    acc[e][3] += tv * w.w;
                }
            }
        }

        // ---- epilogue: msg = h_n * (theta + b2); atomicAdd into agg[center] ----
        float4 b2v = ((const float4*)b2)[cg2];
        #pragma unroll
        for (int e = 0; e < 4; e++) {
            int er = eg2 * 4 + e;
            int ctr = s_ci[er];
            float4 hn = ((const float4*)(s_hn + er * EMBED))[cg2];
            float* dst = g_agg + (size_t)ctr * EMBED + 4 * cg2;
            atomicAdd(dst + 0, hn.x * (acc[e][0] + b2v.x));
            atomicAdd(dst + 1, hn.y * (acc[e][1] + b2v.y));
            atomicAdd(dst + 2, hn.z * (acc[e][2] + b2v.z));
            atomicAdd(dst + 3, hn.w * (acc[e][3] + b2v.w));
        }
    }
}

// ---------------------------------------------------------------------------
// Kernel 3: out = silu(h + agg) @ Wt + bt   (32 node rows per CTA)
// ---------------------------------------------------------------------------
__global__ __launch_bounds__(256)
void out_kernel(const float* __restrict__ Wt, const float* __restrict__ bt,
                float* __restrict__ out) {
    __shared__ float s_x[32 * EMBED];   // 16KB
    __shared__ float s_w[32 * EMBED];   // 16KB

    int tid = threadIdx.x;
    int n0 = blockIdx.x * 32;

    #pragma unroll
    for (int r = 0; r < 4; r++) {
        int v = tid + 256 * r;
        int e = v >> 5;
        int c = v & 31;
        int row = n0 + e;
        float4 xv = make_float4(0.f, 0.f, 0.f, 0.f);
        if (row < N_NODES) {
            float4 hv = ((const float4*)(g_h + (size_t)row * EMBED))[c];
            float4 av = ((const float4*)(g_agg + (size_t)row * EMBED))[c];
            xv.x = silu_f(hv.x + av.x);
            xv.y = silu_f(hv.y + av.y);
            xv.z = silu_f(hv.z + av.z);
            xv.w = silu_f(hv.w + av.w);
        }
        ((float4*)s_x)[v] = xv;
    }

    int cg = tid & 31;   // cols 4*cg..4*cg+3
    int eg = tid >> 5;   // rows eg*4..eg*4+3
    float acc[4][4];
    #pragma unroll
    for (int e = 0; e < 4; e++)
        #pragma unroll
        for (int i = 0; i < 4; i++) acc[e][i] = 0.f;

    for (int kc = 0; kc < EMBED; kc += 32) {
        __syncthreads();
        #pragma unroll
        for (int r = 0; r < 4; r++) {
            int v = tid + 256 * r;
            ((float4*)s_w)[v] = ((const float4*)(Wt + (size_t)kc * EMBED))[v];
        }
        __syncthreads();
        #pragma unroll
        for (int k = 0; k < 32; k++) {
            float4 w = ((const float4*)(s_w + k * EMBED))[cg];
            #pragma unroll
            for (int e = 0; e < 4; e++) {
                float xv = s_x[(eg * 4 + e) * EMBED + kc + k];
                acc[e][0] += xv * w.x;
                acc[e][1] += xv * w.y;
                acc[e][2] += xv * w.z;
                acc[e][3] += xv * w.w;
            }
        }
    }

    float4 btv = ((const float4*)bt)[cg];
    #pragma unroll
    for (int e = 0; e < 4; e++) {
        int row = n0 + eg * 4 + e;
        if (row < N_NODES) {
            float4 o;
            o.x = acc[e][0] + btv.x;
            o.y = acc[e][1] + btv.y;
            o.z = acc[e][2] + btv.z;
            o.w = acc[e][3] + btv.w;
            ((float4*)(out + (size_t)row * EMBED))[cg] = o;
        }
    }
}

// ---------------------------------------------------------------------------
extern "C" void kernel_launch(void* const* d_in, const int* in_sizes, int n_in,
                              void* d_out, int out_size) {
    const float* node  = (const float*)d_in[0];
    const float* eemb  = (const float*)d_in[1];
    const int*   eidx  = (const int*)  d_in[2];
    const float* gamma = (const float*)d_in[3];
    const float* beta  = (const float*)d_in[4];
    const float* W1    = (const float*)d_in[5];
    const float* b1    = (const float*)d_in[6];
    const float* W2    = (const float*)d_in[7];
    const float* b2    = (const float*)d_in[8];
    const float* Wt    = (const float*)d_in[9];
    const float* bt    = (const float*)d_in[10];
    float* out = (float*)d_out;

    const size_t EDGE_SMEM =
        (TILE_E * EMBED + TILE_E * EMBED + TILE_E * HIDDEN + 32 * HIDDEN) * sizeof(float)
        + 2 * TILE_E * sizeof(int);
    cudaFuncSetAttribute(edge_kernel, cudaFuncAttributeMaxDynamicSharedMemorySize,
                         (int)EDGE_SMEM);

    ln_kernel<<<(N_NODES + 7) / 8, 256>>>(node, gamma, beta);
    edge_kernel<<<N_EDGES / TILE_E, ETHREADS, EDGE_SMEM>>>(eemb, eidx, W1, b1, W2, b2);
    out_kernel<<<(N_NODES + 31) / 32, 256>>>(Wt, bt, out);
}

// round 3
// speedup vs baseline: 1.0259x; 1.0259x over previous
#include <cuda_runtime.h>

#define N_NODES 50000
#define EMBED 128
#define HIDDEN 256
#define N_EDGES 640000
#define LN_EPS 1e-5f

typedef unsigned long long u64t;

// Packed 2xfp32 FMA — ptxas never auto-fuses; must come from PTX (SASS: FFMA2)
#define FMA2(d, a, b, c) \
    asm("fma.rn.f32x2 %0, %1, %2, %3;" : "=l"(d) : "l"(a), "l"(b), "l"(c))
#define DUP2(d, x) \
    asm("mov.b64 %0, {%1, %1};" : "=l"(d) : "f"(x))
#define UNPK2(lo, hi, p) \
    asm("mov.b64 {%0, %1}, %2;" : "=f"(lo), "=f"(hi) : "l"(p))

// Scratch (allocation-free rule: __device__ globals)
__device__ float g_h[N_NODES * EMBED];     // layernormed node embeddings
__device__ float g_agg[N_NODES * EMBED];   // segment-sum accumulator

__device__ __forceinline__ float silu_f(float x) {
    return __fdividef(x, 1.0f + __expf(-x));
}

// ---------------------------------------------------------------------------
// Kernel 1: LayerNorm over each node row (warp per row) + zero g_agg
// ---------------------------------------------------------------------------
__global__ void ln_kernel(const float* __restrict__ x,
                          const float* __restrict__ gamma,
                          const float* __restrict__ beta) {
    int warp = (blockIdx.x * blockDim.x + threadIdx.x) >> 5;
    int lane = threadIdx.x & 31;
    if (warp >= N_NODES) return;

    const float4* row = (const float4*)(x + (size_t)warp * EMBED);
    float4 v = row[lane];
    float s  = v.x + v.y + v.z + v.w;
    float ss = v.x * v.x + v.y * v.y + v.z * v.z + v.w * v.w;
    #pragma unroll
    for (int o = 16; o; o >>= 1) {
        s  += __shfl_xor_sync(0xFFFFFFFFu, s,  o);
        ss += __shfl_xor_sync(0xFFFFFFFFu, ss, o);
    }
    const float inv_d = 1.0f / (float)EMBED;
    float mu  = s * inv_d;
    float var = ss * inv_d - mu * mu;
    float inv = rsqrtf(var + LN_EPS);

    float4 g = ((const float4*)gamma)[lane];
    float4 b = ((const float4*)beta)[lane];
    float4 o4;
    o4.x = (v.x - mu) * inv * g.x + b.x;
    o4.y = (v.y - mu) * inv * g.y + b.y;
    o4.z = (v.z - mu) * inv * g.z + b.z;
    o4.w = (v.w - mu) * inv * g.w + b.w;
    ((float4*)(g_h + (size_t)warp * EMBED))[lane] = o4;
    ((float4*)(g_agg + (size_t)warp * EMBED))[lane] = make_float4(0.f, 0.f, 0.f, 0.f);
}

// ---------------------------------------------------------------------------
// Kernel 2: per-edge MLP + scatter-add, FFMA2 inner loops
// ---------------------------------------------------------------------------
#define TILE_E 32
#define ETHREADS 256

__global__ __launch_bounds__(ETHREADS)
void edge_kernel(const float* __restrict__ eemb,
                 const int* __restrict__ eidx,
                 const float* __restrict__ W1, const float* __restrict__ b1,
                 const float* __restrict__ W2, const float* __restrict__ b2) {
    extern __shared__ float sm[];
    float* s_s  = sm;                          // [32][128] silu(s)
    float* s_hn = s_s  + TILE_E * EMBED;       // [32][128] h_n
    float* s_t  = s_hn + TILE_E * EMBED;       // [32][256] silu(t)
    float* s_w  = s_t  + TILE_E * HIDDEN;      // [32][256] weight chunk
    int*   s_ci = (int*)(s_w + 32 * HIDDEN);   // [32] center idx
    int*   s_ni = s_ci + TILE_E;               // [32] neighbor idx

    int tid = threadIdx.x;
    int e0 = blockIdx.x * TILE_E;

    if (tid < TILE_E) {
        s_ci[tid] = eidx[e0 + tid];
        s_ni[tid] = eidx[N_EDGES + e0 + tid];
    }
    __syncthreads();

    // ---- Load + fuse: s = silu(e + h_c + h_n), keep h_n ----
    #pragma unroll
    for (int r = 0; r < 4; r++) {
        int v = tid + ETHREADS * r;     // 0..1023 float4 slots
        int e = v >> 5;                 // edge within tile
        int c = v & 31;                 // float4 column
        float4 ee = ((const float4*)(eemb + (size_t)(e0 + e) * EMBED))[c];
        float4 hc = ((const float4*)(g_h + (size_t)s_ci[e] * EMBED))[c];
        float4 hn = ((const float4*)(g_h + (size_t)s_ni[e] * EMBED))[c];
        float4 sv;
        sv.x = silu_f(ee.x + hc.x + hn.x);
        sv.y = silu_f(ee.y + hc.y + hn.y);
        sv.z = silu_f(ee.z + hc.z + hn.z);
        sv.w = silu_f(ee.w + hc.w + hn.w);
        ((float4*)(s_s  + e * EMBED))[c] = sv;
        ((float4*)(s_hn + e * EMBED))[c] = hn;
    }
    __syncthreads();

    // ---- GEMM1: t[32][256] = silu_s[32][128] @ W1[128][256] ----
    // thread -> cols 4*cg..4*cg+3 (cg = tid%64), edges eg*8..eg*8+7 (eg = tid/64)
    {
        int cg = tid & 63;
        int eg = tid >> 6;
        u64t acc[8][2];
        #pragma unroll
        for (int e = 0; e < 8; e++) { acc[e][0] = 0ull; acc[e][1] = 0ull; }

        for (int kc = 0; kc < EMBED; kc += 32) {
            __syncthreads();   // protect s_w from previous chunk's readers
            #pragma unroll
            for (int r = 0; r < 8; r++) {
                int v = tid + ETHREADS * r;   // 0..2047 float4
                ((float4*)s_w)[v] = ((const float4*)(W1 + (size_t)kc * HIDDEN))[v];
            }
            __syncthreads();
            #pragma unroll
            for (int k = 0; k < 32; k++) {
                ulonglong2 w2 = ((const ulonglong2*)(s_w + k * HIDDEN))[cg];
                #pragma unroll
                for (int e = 0; e < 8; e++) {
                    float sv = s_s[(eg * 8 + e) * EMBED + kc + k];   // warp-broadcast
                    u64t sv2; DUP2(sv2, sv);
                    FMA2(acc[e][0], sv2, w2.x, acc[e][0]);
                    FMA2(acc[e][1], sv2, w2.y, acc[e][1]);
                }
            }
        }
        float4 bb = ((const float4*)b1)[cg];
        #pragma unroll
        for (int e = 0; e < 8; e++) {
            float a0, a1, a2, a3;
            UNPK2(a0, a1, acc[e][0]);
            UNPK2(a2, a3, acc[e][1]);
            float4 tv;
            tv.x = silu_f(a0 + bb.x);
            tv.y = silu_f(a1 + bb.y);
            tv.z = silu_f(a2 + bb.z);
            tv.w = silu_f(a3 + bb.w);
            ((float4*)(s_t + (eg * 8 + e) * HIDDEN))[cg] = tv;
        }
    }

    // ---- GEMM2: theta[32][128] = silu_t[32][256] @ W2[256][128] ----
    // thread -> cols 4*cg2..4*cg2+3 (cg2 = tid%32), edges eg2*4..eg2*4+3 (eg2 = tid/32)
    {
        int cg2 = tid & 31;
        int eg2 = tid >> 5;
        u64t acc[4][2];
        #pragma unroll
        for (int e = 0; e < 4; e++) { acc[e][0] = 0ull; acc[e][1] = 0ull; }

        for (int kc = 0; kc < HIDDEN; kc += 32) {
            __syncthreads();   // s_t stores done (first iter) / s_w readers done
            #pragma unroll
            for (int r = 0; r < 4; r++) {
                int v = tid + ETHREADS * r;   // 0..1023 float4
                ((float4*)s_w)[v] = ((const float4*)(W2 + (size_t)kc * EMBED))[v];
            }
            __syncthreads();
            #pragma unroll
            for (int k = 0; k < 32; k++) {
                ulonglong2 w2 = ((const ulonglong2*)(s_w + k * EMBED))[cg2];
                #pragma unroll
                for (int e = 0; e < 4; e++) {
                    float tv = s_t[(eg2 * 4 + e) * HIDDEN + kc + k];  // warp-broadcast
                    u64t tv2; DUP2(tv2, tv);
                    FMA2(acc[e][0], tv2, w2.x, acc[e][0]);
                    FMA2(acc[e][1], tv2, w2.y, acc[e][1]);
                }
            }
        }

        // ---- epilogue: msg = h_n * (theta + b2); atomicAdd into agg[center] ----
        float4 b2v = ((const float4*)b2)[cg2];
        #pragma unroll
        for (int e = 0; e < 4; e++) {
            int er = eg2 * 4 + e;
            int ctr = s_ci[er];
            float a0, a1, a2, a3;
            UNPK2(a0, a1, acc[e][0]);
            UNPK2(a2, a3, acc[e][1]);
            float4 hn = ((const float4*)(s_hn + er * EMBED))[cg2];
            float* dst = g_agg + (size_t)ctr * EMBED + 4 * cg2;
            atomicAdd(dst + 0, hn.x * (a0 + b2v.x));
            atomicAdd(dst + 1, hn.y * (a1 + b2v.y));
            atomicAdd(dst + 2, hn.z * (a2 + b2v.z));
            atomicAdd(dst + 3, hn.w * (a3 + b2v.w));
        }
    }
}

// ---------------------------------------------------------------------------
// Kernel 3: out = silu(h + agg) @ Wt + bt   (32 node rows per CTA), FFMA2
// ---------------------------------------------------------------------------
__global__ __launch_bounds__(256)
void out_kernel(const float* __restrict__ Wt, const float* __restrict__ bt,
                float* __restrict__ out) {
    __shared__ float s_x[32 * EMBED];   // 16KB
    __shared__ float s_w[32 * EMBED];   // 16KB

    int tid = threadIdx.x;
    int n0 = blockIdx.x * 32;

    #pragma unroll
    for (int r = 0; r < 4; r++) {
        int v = tid + 256 * r;
        int e = v >> 5;
        int c = v & 31;
        int row = n0 + e;
        float4 xv = make_float4(0.f, 0.f, 0.f, 0.f);
        if (row < N_NODES) {
            float4 hv = ((const float4*)(g_h + (size_t)row * EMBED))[c];
            float4 av = ((const float4*)(g_agg + (size_t)row * EMBED))[c];
            xv.x = silu_f(hv.x + av.x);
            xv.y = silu_f(hv.y + av.y);
            xv.z = silu_f(hv.z + av.z);
            xv.w = silu_f(hv.w + av.w);
        }
        ((float4*)s_x)[v] = xv;
    }

    int cg = tid & 31;   // cols 4*cg..4*cg+3
    int eg = tid >> 5;   // rows eg*4..eg*4+3
    u64t acc[4][2];
    #pragma unroll
    for (int e = 0; e < 4; e++) { acc[e][0] = 0ull; acc[e][1] = 0ull; }

    for (int kc = 0; kc < EMBED; kc += 32) {
        __syncthreads();
        #pragma unroll
        for (int r = 0; r < 4; r++) {
            int v = tid + 256 * r;
            ((float4*)s_w)[v] = ((const float4*)(Wt + (size_t)kc * EMBED))[v];
        }
        __syncthreads();
        #pragma unroll
        for (int k = 0; k < 32; k++) {
            ulonglong2 w2 = ((const ulonglong2*)(s_w + k * EMBED))[cg];
            #pragma unroll
            for (int e = 0; e < 4; e++) {
                float xv = s_x[(eg * 4 + e) * EMBED + kc + k];
                u64t xv2; DUP2(xv2, xv);
                FMA2(acc[e][0], xv2, w2.x, acc[e][0]);
                FMA2(acc[e][1], xv2, w2.y, acc[e][1]);
            }
        }
    }

    float4 btv = ((const float4*)bt)[cg];
    #pragma unroll
    for (int e = 0; e < 4; e++) {
        int row = n0 + eg * 4 + e;
        if (row < N_NODES) {
            float a0, a1, a2, a3;
            UNPK2(a0, a1, acc[e][0]);
            UNPK2(a2, a3, acc[e][1]);
            float4 o;
            o.x = a0 + btv.x;
            o.y = a1 + btv.y;
            o.z = a2 + btv.z;
            o.w = a3 + btv.w;
            ((float4*)(out + (size_t)row * EMBED))[cg] = o;
        }
    }
}

// ---------------------------------------------------------------------------
extern "C" void kernel_launch(void* const* d_in, const int* in_sizes, int n_in,
                              void* d_out, int out_size) {
    const float* node  = (const float*)d_in[0];
    const float* eemb  = (const float*)d_in[1];
    const int*   eidx  = (const int*)  d_in[2];
    const float* gamma = (const float*)d_in[3];
    const float* beta  = (const float*)d_in[4];
    const float* W1    = (const float*)d_in[5];
    const float* b1    = (const float*)d_in[6];
    const float* W2    = (const float*)d_in[7];
    const float* b2    = (const float*)d_in[8];
    const float* Wt    = (const float*)d_in[9];
    const float* bt    = (const float*)d_in[10];
    float* out = (float*)d_out;

    const size_t EDGE_SMEM =
        (TILE_E * EMBED + TILE_E * EMBED + TILE_E * HIDDEN + 32 * HIDDEN) * sizeof(float)
        + 2 * TILE_E * sizeof(int);
    cudaFuncSetAttribute(edge_kernel, cudaFuncAttributeMaxDynamicSharedMemorySize,
                         (int)EDGE_SMEM);

    ln_kernel<<<(N_NODES + 7) / 8, 256>>>(node, gamma, beta);
    edge_kernel<<<N_EDGES / TILE_E, ETHREADS, EDGE_SMEM>>>(eemb, eidx, W1, b1, W2, b2);
    out_kernel<<<(N_NODES + 31) / 32, 256>>>(Wt, bt, out);
}

// round 5
// speedup vs baseline: 1.2280x; 1.1970x over previous
#include <cuda_runtime.h>
#include <cuda_bf16.h>
#include <cstdint>

#define N_NODES 50000
#define EMBED 128
#define HIDDEN 256
#define N_EDGES 640000
#define LN_EPS 1e-5f

typedef unsigned long long u64t;

// ---------------- FFMA2 helpers (out_kernel) ----------------
#define FMA2(d, a, b, c) \
    asm("fma.rn.f32x2 %0, %1, %2, %3;" : "=l"(d) : "l"(a), "l"(b), "l"(c))
#define DUP2(d, x) \
    asm("mov.b64 %0, {%1, %1};" : "=l"(d) : "f"(x))
#define UNPK2(lo, hi, p) \
    asm("mov.b64 {%0, %1}, %2;" : "=f"(lo), "=f"(hi) : "l"(p))

// ---------------- warp MMA helpers (sm_80-class, OK on plain sm_103) --------
__device__ __forceinline__ uint32_t smem_u32(const void* p) {
    uint32_t a;
    asm("{ .reg .u64 t; cvta.to.shared.u64 t, %1; cvt.u32.u64 %0, t; }"
        : "=r"(a) : "l"(p));
    return a;
}
__device__ __forceinline__ void mma_bf16(float* d, const uint32_t* a, const uint32_t* b) {
    asm volatile(
        "mma.sync.aligned.m16n8k16.row.col.f32.bf16.bf16.f32 "
        "{%0,%1,%2,%3}, {%4,%5,%6,%7}, {%8,%9}, {%0,%1,%2,%3};"
        : "+f"(d[0]), "+f"(d[1]), "+f"(d[2]), "+f"(d[3])
        : "r"(a[0]), "r"(a[1]), "r"(a[2]), "r"(a[3]), "r"(b[0]), "r"(b[1]));
}
__device__ __forceinline__ void ldm4(uint32_t* r, uint32_t addr) {
    asm volatile("ldmatrix.sync.aligned.m8n8.x4.shared.b16 {%0,%1,%2,%3}, [%4];"
                 : "=r"(r[0]), "=r"(r[1]), "=r"(r[2]), "=r"(r[3]) : "r"(addr));
}
__device__ __forceinline__ void ldm2(uint32_t* r, uint32_t addr) {
    asm volatile("ldmatrix.sync.aligned.m8n8.x2.shared.b16 {%0,%1}, [%2];"
                 : "=r"(r[0]), "=r"(r[1]) : "r"(addr));
}

// pack two fp32 -> bf16x2 (element0 in low half) — layout-safe via __nv_bfloat162
__device__ __forceinline__ uint32_t pack_bf16x2(float lo, float hi) {
    __nv_bfloat162 p;
    p.x = __float2bfloat16_rn(lo);
    p.y = __float2bfloat16_rn(hi);
    return *(uint32_t*)&p;
}
__device__ __forceinline__ float bf_hi(float x) {
    return __bfloat162float(__float2bfloat16_rn(x));
}
__device__ __forceinline__ float silu_f(float x) {
    return __fdividef(x, 1.0f + __expf(-x));
}

// ---------------- device scratch ----------------
__device__ float g_h[N_NODES * EMBED];
__device__ float g_agg[N_NODES * EMBED];
// pre-transposed bf16 hi/lo weight images: w1 [n=256][k=128], w2 [n=128][k=256]
__device__ __nv_bfloat16 g_w1hi[32768], g_w1lo[32768];
__device__ __nv_bfloat16 g_w2hi[32768], g_w2lo[32768];

// ---------------------------------------------------------------------------
// Prep: split W1/W2 into bf16 hi/lo transposed images
// ---------------------------------------------------------------------------
__global__ void prep_kernel(const float* __restrict__ W1, const float* __restrict__ W2) {
    int idx = blockIdx.x * blockDim.x + threadIdx.x;
    if (idx >= 32768) return;
    {   // W1 [k=128][n=256] -> [n][k]
        int k = idx >> 8, n = idx & 255;
        float w = W1[idx];
        __nv_bfloat16 h = __float2bfloat16_rn(w);
        g_w1hi[n * 128 + k] = h;
        g_w1lo[n * 128 + k] = __float2bfloat16_rn(w - __bfloat162float(h));
    }
    {   // W2 [kk=256][n=128] -> [n][kk]
        int kk = idx >> 7, n = idx & 127;
        float w = W2[idx];
        __nv_bfloat16 h = __float2bfloat16_rn(w);
        g_w2hi[n * 256 + kk] = h;
        g_w2lo[n * 256 + kk] = __float2bfloat16_rn(w - __bfloat162float(h));
    }
}

// ---------------------------------------------------------------------------
// Kernel 1: LayerNorm (warp per row) + zero g_agg
// ---------------------------------------------------------------------------
__global__ void ln_kernel(const float* __restrict__ x,
                          const float* __restrict__ gamma,
                          const float* __restrict__ beta) {
    int warp = (blockIdx.x * blockDim.x + threadIdx.x) >> 5;
    int lane = threadIdx.x & 31;
    if (warp >= N_NODES) return;

    const float4* row = (const float4*)(x + (size_t)warp * EMBED);
    float4 v = row[lane];
    float s  = v.x + v.y + v.z + v.w;
    float ss = v.x * v.x + v.y * v.y + v.z * v.z + v.w * v.w;
    #pragma unroll
    for (int o = 16; o; o >>= 1) {
        s  += __shfl_xor_sync(0xFFFFFFFFu, s,  o);
        ss += __shfl_xor_sync(0xFFFFFFFFu, ss, o);
    }
    const float inv_d = 1.0f / (float)EMBED;
    float mu  = s * inv_d;
    float var = ss * inv_d - mu * mu;
    float inv = rsqrtf(var + LN_EPS);

    float4 g = ((const float4*)gamma)[lane];
    float4 b = ((const float4*)beta)[lane];
    float4 o4;
    o4.x = (v.x - mu) * inv * g.x + b.x;
    o4.y = (v.y - mu) * inv * g.y + b.y;
    o4.z = (v.z - mu) * inv * g.z + b.z;
    o4.w = (v.w - mu) * inv * g.w + b.w;
    ((float4*)(g_h + (size_t)warp * EMBED))[lane] = o4;
    ((float4*)(g_agg + (size_t)warp * EMBED))[lane] = make_float4(0.f, 0.f, 0.f, 0.f);
}

// ---------------------------------------------------------------------------
// Kernel 2: mma.sync edge MLP. 128 edges/CTA, 8 warps (16 rows each).
// ---------------------------------------------------------------------------
#define TE 128
#define ETH 256
#define A_STRIDE 264   // halves; row stride 528B -> 16B-rotating, ldmatrix conflict-free
#define B_STRIDE 136   // halves; 272B rows

#define SM_CI   0
#define SM_NI   512
#define SM_B1   1024
#define SM_B2   2048
#define SM_A_HI 2560
#define SM_A_LO (SM_A_HI + 128 * A_STRIDE * 2)   // 70144
#define SM_B_HI (SM_A_LO + 128 * A_STRIDE * 2)   // 137728
#define SM_B_LO (SM_B_HI + 128 * B_STRIDE * 2)   // 172544
#define EDGE_SMEM (SM_B_LO + 128 * B_STRIDE * 2) // 207360

__device__ __forceinline__ void copy_tile(char* smem, int dst_off,
                                          const __nv_bfloat16* __restrict__ src,
                                          int src_stride_halves, int tid) {
    // 128 rows x 128 halves (16 uint4 per row)
    #pragma unroll
    for (int i = tid; i < 2048; i += ETH) {
        int r = i >> 4, c = i & 15;
        *(uint4*)(smem + dst_off + r * (B_STRIDE * 2) + c * 16) =
            *(const uint4*)(src + r * src_stride_halves + c * 8);
    }
}

__global__ __launch_bounds__(ETH, 1)
void edge_kernel(const float* __restrict__ eemb,
                 const int* __restrict__ eidx,
                 const float* __restrict__ b1g,
                 const float* __restrict__ b2g) {
    extern __shared__ char smem[];
    uint32_t sbase = smem_u32(smem);
    int tid = threadIdx.x, wid = tid >> 5, lane = tid & 31;
    int e0 = blockIdx.x * TE;

    int*   s_ci = (int*)(smem + SM_CI);
    int*   s_ni = (int*)(smem + SM_NI);
    float* sb1  = (float*)(smem + SM_B1);
    float* sb2  = (float*)(smem + SM_B2);

    if (tid < 128) {
        s_ci[tid] = eidx[e0 + tid];
        s_ni[tid] = eidx[N_EDGES + e0 + tid];
    }
    sb1[tid] = b1g[tid];
    if (tid < 128) sb2[tid] = b2g[tid];
    __syncthreads();

    // ---- build A1 = split(silu(e + h_c + h_n)) into smem hi/lo planes ----
    #pragma unroll
    for (int it = 0; it < 16; it++) {
        int v = tid + ETH * it;       // 0..4095
        int m = v >> 5, c = v & 31;   // edge row, float4 col (k = 4c..4c+3)
        float4 ee = ((const float4*)(eemb + (size_t)(e0 + m) * EMBED))[c];
        float4 hc = ((const float4*)(g_h + (size_t)s_ci[m] * EMBED))[c];
        float4 hn = ((const float4*)(g_h + (size_t)s_ni[m] * EMBED))[c];
        float s0 = silu_f(ee.x + hc.x + hn.x);
        float s1 = silu_f(ee.y + hc.y + hn.y);
        float s2 = silu_f(ee.z + hc.z + hn.z);
        float s3 = silu_f(ee.w + hc.w + hn.w);
        uint2 uh, ul;
        uh.x = pack_bf16x2(s0, s1);
        uh.y = pack_bf16x2(s2, s3);
        ul.x = pack_bf16x2(s0 - bf_hi(s0), s1 - bf_hi(s1));
        ul.y = pack_bf16x2(s2 - bf_hi(s2), s3 - bf_hi(s3));
        int off = (m * A_STRIDE + 4 * c) * 2;
        *(uint2*)(smem + SM_A_HI + off) = uh;
        *(uint2*)(smem + SM_A_LO + off) = ul;
    }

    int rb = wid * 16;
    int ai = lane & 7, as_ = lane >> 3;
    int arow = rb + ai + (as_ & 1) * 8;
    int acolseg = (as_ >> 1) * 8;
    int bi = lane & 7, bs = (lane >> 3) & 1;
    int q = lane & 3;

    // ---- GEMM1: acc1[m16 x n256] over K=128, 3-term bf16 split ----
    float acc1[32][4];
    #pragma unroll
    for (int i = 0; i < 32; i++)
        #pragma unroll
        for (int j = 0; j < 4; j++) acc1[i][j] = 0.f;

    #pragma unroll 1
    for (int h = 0; h < 2; h++) {
        __syncthreads();   // prior B consumers done (and A1 stores visible, h=0)
        copy_tile(smem, SM_B_HI, g_w1hi + h * 128 * 128, 128, tid);
        copy_tile(smem, SM_B_LO, g_w1lo + h * 128 * 128, 128, tid);
        __syncthreads();
        #pragma unroll
        for (int ks = 0; ks < 8; ks++) {
            uint32_t ahi[4], alo[4];
            uint32_t aoff = (uint32_t)(arow * A_STRIDE + ks * 16 + acolseg) * 2;
            ldm4(ahi, sbase + SM_A_HI + aoff);
            ldm4(alo, sbase + SM_A_LO + aoff);
            #pragma unroll
            for (int nt = 0; nt < 16; nt++) {
                uint32_t boff = (uint32_t)((nt * 8 + bi) * B_STRIDE + ks * 16 + bs * 8) * 2;
                uint32_t bhi[2], blo[2];
                ldm2(bhi, sbase + SM_B_HI + boff);
                ldm2(blo, sbase + SM_B_LO + boff);
                float* d = acc1[h * 16 + nt];
                mma_bf16(d, ahi, bhi);
                mma_bf16(d, ahi, blo);
                mma_bf16(d, alo, bhi);
            }
        }
    }

    // ---- conversion: t = silu(acc1 + b1) -> bf16 hi/lo back into A region ----
    // (each warp touches only its own 16 rows; cross-warp sync happens at GEMM2 copy)
    {
        int r0 = rb + (lane >> 2), r1 = r0 + 8;
        #pragma unroll
        for (int nt = 0; nt < 32; nt++) {
            int c0 = nt * 8 + 2 * q;
            float t0 = silu_f(acc1[nt][0] + sb1[c0]);
            float t1 = silu_f(acc1[nt][1] + sb1[c0 + 1]);
            float t2 = silu_f(acc1[nt][2] + sb1[c0]);
            float t3 = silu_f(acc1[nt][3] + sb1[c0 + 1]);
            int o0 = (r0 * A_STRIDE + c0) * 2;
            int o1 = (r1 * A_STRIDE + c0) * 2;
            *(uint32_t*)(smem + SM_A_HI + o0) = pack_bf16x2(t0, t1);
            *(uint32_t*)(smem + SM_A_LO + o0) =
                pack_bf16x2(t0 - bf_hi(t0), t1 - bf_hi(t1));
            *(uint32_t*)(smem + SM_A_HI + o1) = pack_bf16x2(t2, t3);
            *(uint32_t*)(smem + SM_A_LO + o1) =
                pack_bf16x2(t2 - bf_hi(t2), t3 - bf_hi(t3));
        }
    }

    // ---- GEMM2: acc2[m16 x n128] over K=256 in two k-halves ----
    float acc2[16][4];
    #pragma unroll
    for (int i = 0; i < 16; i++)
        #pragma unroll
        for (int j = 0; j < 4; j++) acc2[i][j] = 0.f;

    #pragma unroll 1
    for (int kh = 0; kh < 2; kh++) {
        __syncthreads();   // GEMM1 B reads + conversion stores complete
        copy_tile(smem, SM_B_HI, g_w2hi + kh * 128, 256, tid);
        copy_tile(smem, SM_B_LO, g_w2lo + kh * 128, 256, tid);
        __syncthreads();
        #pragma unroll
        for (int ks = 0; ks < 8; ks++) {
            int g = kh * 8 + ks;
            uint32_t ahi[4], alo[4];
            uint32_t aoff = (uint32_t)(arow * A_STRIDE + g * 16 + acolseg) * 2;
            ldm4(ahi, sbase + SM_A_HI + aoff);
            ldm4(alo, sbase + SM_A_LO + aoff);
            #pragma unroll
            for (int nt = 0; nt < 16; nt++) {
                uint32_t boff = (uint32_t)((nt * 8 + bi) * B_STRIDE + ks * 16 + bs * 8) * 2;
                uint32_t bhi[2], blo[2];
                ldm2(bhi, sbase + SM_B_HI + boff);
                ldm2(blo, sbase + SM_B_LO + boff);
                mma_bf16(acc2[nt], ahi, bhi);
                mma_bf16(acc2[nt], ahi, blo);
                mma_bf16(acc2[nt], alo, bhi);
            }
        }
    }

    // ---- epilogue: msg = h_n * (acc2 + b2); atomicAdd into g_agg[center] ----
    {
        int r0 = rb + (lane >> 2), r1 = r0 + 8;
        int ci0 = s_ci[r0], ci1 = s_ci[r1];
        int ni0 = s_ni[r0], ni1 = s_ni[r1];
        const float* hn0 = g_h + (size_t)ni0 * EMBED;
        const float* hn1 = g_h + (size_t)ni1 * EMBED;
        float* ag0 = g_agg + (size_t)ci0 * EMBED;
        float* ag1 = g_agg + (size_t)ci1 * EMBED;
        #pragma unroll
        for (int nt = 0; nt < 16; nt++) {
            int c0 = nt * 8 + 2 * q;
            float2 h0 = *(const float2*)(hn0 + c0);
            float2 h1 = *(const float2*)(hn1 + c0);
            atomicAdd(ag0 + c0,     (acc2[nt][0] + sb2[c0])     * h0.x);
            atomicAdd(ag0 + c0 + 1, (acc2[nt][1] + sb2[c0 + 1]) * h0.y);
            atomicAdd(ag1 + c0,     (acc2[nt][2] + sb2[c0])     * h1.x);
            atomicAdd(ag1 + c0 + 1, (acc2[nt][3] + sb2[c0 + 1]) * h1.y);
        }
    }
}

// ---------------------------------------------------------------------------
// Kernel 3: out = silu(h + agg) @ Wt + bt   (FFMA2 scalar path)
// ---------------------------------------------------------------------------
__global__ __launch_bounds__(256)
void out_kernel(const float* __restrict__ Wt, const float* __restrict__ bt,
                float* __restrict__ out) {
    __shared__ float s_x[32 * EMBED];
    __shared__ float s_w[32 * EMBED];

    int tid = threadIdx.x;
    int n0 = blockIdx.x * 32;

    #pragma unroll
    for (int r = 0; r < 4; r++) {
        int v = tid + 256 * r;
        int e = v >> 5;
        int c = v & 31;
        int row = n0 + e;
        float4 xv = make_float4(0.f, 0.f, 0.f, 0.f);
        if (row < N_NODES) {
            float4 hv = ((const float4*)(g_h + (size_t)row * EMBED))[c];
            float4 av = ((const float4*)(g_agg + (size_t)row * EMBED))[c];
            xv.x = silu_f(hv.x + av.x);
            xv.y = silu_f(hv.y + av.y);
            xv.z = silu_f(hv.z + av.z);
            xv.w = silu_f(hv.w + av.w);
        }
        ((float4*)s_x)[v] = xv;
    }

    int cg = tid & 31;
    int eg = tid >> 5;
    u64t acc[4][2];
    #pragma unroll
    for (int e = 0; e < 4; e++) { acc[e][0] = 0ull; acc[e][1] = 0ull; }

    for (int kc = 0; kc < EMBED; kc += 32) {
        __syncthreads();
        #pragma unroll
        for (int r = 0; r < 4; r++) {
            int v = tid + 256 * r;
            ((float4*)s_w)[v] = ((const float4*)(Wt + (size_t)kc * EMBED))[v];
        }
        __syncthreads();
        #pragma unroll
        for (int k = 0; k < 32; k++) {
            ulonglong2 w2 = ((const ulonglong2*)(s_w + k * EMBED))[cg];
            #pragma unroll
            for (int e = 0; e < 4; e++) {
                float xv = s_x[(eg * 4 + e) * EMBED + kc + k];
                u64t xv2; DUP2(xv2, xv);
                FMA2(acc[e][0], xv2, w2.x, acc[e][0]);
                FMA2(acc[e][1], xv2, w2.y, acc[e][1]);
            }
        }
    }

    float4 btv = ((const float4*)bt)[cg];
    #pragma unroll
    for (int e = 0; e < 4; e++) {
        int row = n0 + eg * 4 + e;
        if (row < N_NODES) {
            float a0, a1, a2, a3;
            UNPK2(a0, a1, acc[e][0]);
            UNPK2(a2, a3, acc[e][1]);
            float4 o;
            o.x = a0 + btv.x;
            o.y = a1 + btv.y;
            o.z = a2 + btv.z;
            o.w = a3 + btv.w;
            ((float4*)(out + (size_t)row * EMBED))[cg] = o;
        }
    }
}

// ---------------------------------------------------------------------------
extern "C" void kernel_launch(void* const* d_in, const int* in_sizes, int n_in,
                              void* d_out, int out_size) {
    const float* node  = (const float*)d_in[0];
    const float* eemb  = (const float*)d_in[1];
    const int*   eidx  = (const int*)  d_in[2];
    const float* gamma = (const float*)d_in[3];
    const float* beta  = (const float*)d_in[4];
    const float* W1    = (const float*)d_in[5];
    const float* b1    = (const float*)d_in[6];
    const float* W2    = (const float*)d_in[7];
    const float* b2    = (const float*)d_in[8];
    const float* Wt    = (const float*)d_in[9];
    const float* bt    = (const float*)d_in[10];
    float* out = (float*)d_out;

    cudaFuncSetAttribute(edge_kernel, cudaFuncAttributeMaxDynamicSharedMemorySize,
                         EDGE_SMEM);

    prep_kernel<<<128, 256>>>(W1, W2);
    ln_kernel<<<(N_NODES + 7) / 8, 256>>>(node, gamma, beta);
    edge_kernel<<<N_EDGES / TE, ETH, EDGE_SMEM>>>(eemb, eidx, b1, b2);
    out_kernel<<<(N_NODES + 31) / 32, 256>>>(Wt, bt, out);
}

// round 6
// speedup vs baseline: 1.3587x; 1.1064x over previous
#include <cuda_runtime.h>
#include <cuda_fp16.h>
#include <cstdint>

#define N_NODES 50000
#define EMBED 128
#define HIDDEN 256
#define N_EDGES 640000
#define LN_EPS 1e-5f

typedef unsigned long long u64t;

// ---------------- FFMA2 helpers (out_kernel) ----------------
#define FMA2(d, a, b, c) \
    asm("fma.rn.f32x2 %0, %1, %2, %3;" : "=l"(d) : "l"(a), "l"(b), "l"(c))
#define DUP2(d, x) \
    asm("mov.b64 %0, {%1, %1};" : "=l"(d) : "f"(x))
#define UNPK2(lo, hi, p) \
    asm("mov.b64 {%0, %1}, %2;" : "=f"(lo), "=f"(hi) : "l"(p))

// ---------------- warp MMA / cp.async helpers (sm_80-class) ----------------
__device__ __forceinline__ uint32_t smem_u32(const void* p) {
    uint32_t a;
    asm("{ .reg .u64 t; cvta.to.shared.u64 t, %1; cvt.u32.u64 %0, t; }"
        : "=r"(a) : "l"(p));
    return a;
}
__device__ __forceinline__ void mma_f16(float* d, const uint32_t* a, const uint32_t* b) {
    asm volatile(
        "mma.sync.aligned.m16n8k16.row.col.f32.f16.f16.f32 "
        "{%0,%1,%2,%3}, {%4,%5,%6,%7}, {%8,%9}, {%0,%1,%2,%3};"
        : "+f"(d[0]), "+f"(d[1]), "+f"(d[2]), "+f"(d[3])
        : "r"(a[0]), "r"(a[1]), "r"(a[2]), "r"(a[3]), "r"(b[0]), "r"(b[1]));
}
__device__ __forceinline__ void ldm4(uint32_t* r, uint32_t addr) {
    asm volatile("ldmatrix.sync.aligned.m8n8.x4.shared.b16 {%0,%1,%2,%3}, [%4];"
                 : "=r"(r[0]), "=r"(r[1]), "=r"(r[2]), "=r"(r[3]) : "r"(addr));
}
__device__ __forceinline__ void ldm2(uint32_t* r, uint32_t addr) {
    asm volatile("ldmatrix.sync.aligned.m8n8.x2.shared.b16 {%0,%1}, [%2];"
                 : "=r"(r[0]), "=r"(r[1]) : "r"(addr));
}
__device__ __forceinline__ void cpa16(uint32_t dst, const void* src) {
    asm volatile("cp.async.cg.shared.global [%0], [%1], 16;" :: "r"(dst), "l"(src));
}
#define CP_COMMIT() asm volatile("cp.async.commit_group;" ::: "memory")
#define CP_WAIT(n)  asm volatile("cp.async.wait_group %0;" :: "n"(n) : "memory")

__device__ __forceinline__ float silu_f(float x) {
    return __fdividef(x, 1.0f + __expf(-x));
}

// ---------------- device scratch ----------------
__device__ float g_h[N_NODES * EMBED];
__device__ float g_agg[N_NODES * EMBED];
// fp16 transposed weight images: w1 [n=256][k=128], w2 [n=128][kk=256]
__device__ __align__(16) __half g_w1h[32768];
__device__ __align__(16) __half g_w2h[32768];

// ---------------------------------------------------------------------------
// Prep: W1/W2 -> fp16 transposed images
// ---------------------------------------------------------------------------
__global__ void prep_kernel(const float* __restrict__ W1, const float* __restrict__ W2) {
    int idx = blockIdx.x * blockDim.x + threadIdx.x;
    if (idx >= 32768) return;
    {   // W1 [k=128][n=256] -> [n][k]
        int k = idx >> 8, n = idx & 255;
        g_w1h[n * 128 + k] = __float2half_rn(W1[idx]);
    }
    {   // W2 [kk=256][n=128] -> [n][kk]
        int kk = idx >> 7, n = idx & 127;
        g_w2h[n * 256 + kk] = __float2half_rn(W2[idx]);
    }
}

// ---------------------------------------------------------------------------
// Kernel 1: LayerNorm (warp per row) + zero g_agg
// ---------------------------------------------------------------------------
__global__ void ln_kernel(const float* __restrict__ x,
                          const float* __restrict__ gamma,
                          const float* __restrict__ beta) {
    int warp = (blockIdx.x * blockDim.x + threadIdx.x) >> 5;
    int lane = threadIdx.x & 31;
    if (warp >= N_NODES) return;

    const float4* row = (const float4*)(x + (size_t)warp * EMBED);
    float4 v = row[lane];
    float s  = v.x + v.y + v.z + v.w;
    float ss = v.x * v.x + v.y * v.y + v.z * v.z + v.w * v.w;
    #pragma unroll
    for (int o = 16; o; o >>= 1) {
        s  += __shfl_xor_sync(0xFFFFFFFFu, s,  o);
        ss += __shfl_xor_sync(0xFFFFFFFFu, ss, o);
    }
    const float inv_d = 1.0f / (float)EMBED;
    float mu  = s * inv_d;
    float var = ss * inv_d - mu * mu;
    float inv = rsqrtf(var + LN_EPS);

    float4 g = ((const float4*)gamma)[lane];
    float4 b = ((const float4*)beta)[lane];
    float4 o4;
    o4.x = (v.x - mu) * inv * g.x + b.x;
    o4.y = (v.y - mu) * inv * g.y + b.y;
    o4.z = (v.z - mu) * inv * g.z + b.z;
    o4.w = (v.w - mu) * inv * g.w + b.w;
    ((float4*)(g_h + (size_t)warp * EMBED))[lane] = o4;
    ((float4*)(g_agg + (size_t)warp * EMBED))[lane] = make_float4(0.f, 0.f, 0.f, 0.f);
}

// ---------------------------------------------------------------------------
// Kernel 2: mma.sync fp16 edge MLP. 128 edges/CTA, 8 warps, A hi/lo split.
// ---------------------------------------------------------------------------
#define TE 128
#define ETH 256
#define A_STRIDE 264   // halves; 528B rows -> 16B-rotating, ldmatrix conflict-free
#define B_STRIDE 136   // halves; 272B rows

#define SM_CI   0
#define SM_NI   512
#define SM_B1   1024
#define SM_B2   2048
#define SM_A_HI 2560
#define SM_A_LO (SM_A_HI + 128 * A_STRIDE * 2)    // 70144
#define SM_BB0  (SM_A_LO + 128 * A_STRIDE * 2)    // 137728
#define SM_BB1  (SM_BB0 + 128 * B_STRIDE * 2)     // 172544
#define EDGE_SMEM (SM_BB1 + 128 * B_STRIDE * 2)   // 207360

// async copy of a 128x128-half tile into padded B buffer (8 x 16B per thread)
__device__ __forceinline__ void cp_tile(uint32_t sdst,
                                        const __half* __restrict__ src,
                                        int src_stride_halves, int tid) {
    #pragma unroll
    for (int i = tid; i < 2048; i += ETH) {
        int r = i >> 4, c = i & 15;
        cpa16(sdst + r * (B_STRIDE * 2) + c * 16,
              src + r * src_stride_halves + c * 8);
    }
}

__global__ __launch_bounds__(ETH, 1)
void edge_kernel(const float* __restrict__ eemb,
                 const int* __restrict__ eidx,
                 const float* __restrict__ b1g,
                 const float* __restrict__ b2g) {
    extern __shared__ char smem[];
    uint32_t sbase = smem_u32(smem);
    int tid = threadIdx.x, wid = tid >> 5, lane = tid & 31;
    int e0 = blockIdx.x * TE;

    int*   s_ci = (int*)(smem + SM_CI);
    int*   s_ni = (int*)(smem + SM_NI);
    float* sb1  = (float*)(smem + SM_B1);
    float* sb2  = (float*)(smem + SM_B2);

    // prefetch W1 halves into both B buffers (overlaps with gather below)
    cp_tile(sbase + SM_BB0, g_w1h, 128, tid);             CP_COMMIT();  // T0
    cp_tile(sbase + SM_BB1, g_w1h + 128 * 128, 128, tid); CP_COMMIT();  // T1

    if (tid < 128) {
        s_ci[tid] = eidx[e0 + tid];
        s_ni[tid] = eidx[N_EDGES + e0 + tid];
    }
    sb1[tid] = b1g[tid];
    if (tid < 128) sb2[tid] = b2g[tid];
    __syncthreads();

    // ---- build A1 = fp16 hi/lo split of silu(e + h_c + h_n) ----
    #pragma unroll
    for (int it = 0; it < 16; it++) {
        int v = tid + ETH * it;       // 0..4095
        int m = v >> 5, c = v & 31;   // edge row, float4 col (k = 4c..4c+3)
        float4 ee = ((const float4*)(eemb + (size_t)(e0 + m) * EMBED))[c];
        float4 hc = ((const float4*)(g_h + (size_t)s_ci[m] * EMBED))[c];
        float4 hn = ((const float4*)(g_h + (size_t)s_ni[m] * EMBED))[c];
        float s0 = silu_f(ee.x + hc.x + hn.x);
        float s1 = silu_f(ee.y + hc.y + hn.y);
        float s2 = silu_f(ee.z + hc.z + hn.z);
        float s3 = silu_f(ee.w + hc.w + hn.w);
        __half h0 = __float2half_rn(s0), h1 = __float2half_rn(s1);
        __half h2 = __float2half_rn(s2), h3 = __float2half_rn(s3);
        __half2 uh0 = __halves2half2(h0, h1);
        __half2 uh1 = __halves2half2(h2, h3);
        __half2 ul0 = __floats2half2_rn(s0 - __half2float(h0), s1 - __half2float(h1));
        __half2 ul1 = __floats2half2_rn(s2 - __half2float(h2), s3 - __half2float(h3));
        int off = (m * A_STRIDE + 4 * c) * 2;
        *(__half2*)(smem + SM_A_HI + off)     = uh0;
        *(__half2*)(smem + SM_A_HI + off + 4) = uh1;
        *(__half2*)(smem + SM_A_LO + off)     = ul0;
        *(__half2*)(smem + SM_A_LO + off + 4) = ul1;
    }

    int rb = wid * 16;
    int ai = lane & 7, as_ = lane >> 3;
    int arow = rb + ai + (as_ & 1) * 8;
    int acolseg = (as_ >> 1) * 8;
    int bi = lane & 7, bs = (lane >> 3) & 1;
    int q = lane & 3;

    // ---- GEMM1: acc1[m16 x n256] over K=128, 2 MMA per (k16,n8) ----
    float acc1[32][4];
    #pragma unroll
    for (int i = 0; i < 32; i++)
        #pragma unroll
        for (int j = 0; j < 4; j++) acc1[i][j] = 0.f;

    #pragma unroll 1
    for (int h = 0; h < 2; h++) {
        if (h == 0) { CP_WAIT(1); }   // T0 ready
        else        { CP_WAIT(1); }   // T1 ready (pending: T2 only)
        __syncthreads();
        uint32_t bbuf = sbase + ((h == 0) ? SM_BB0 : SM_BB1);
        #pragma unroll
        for (int ks = 0; ks < 8; ks++) {
            uint32_t ahi[4], alo[4];
            uint32_t aoff = (uint32_t)(arow * A_STRIDE + ks * 16 + acolseg) * 2;
            ldm4(ahi, sbase + SM_A_HI + aoff);
            ldm4(alo, sbase + SM_A_LO + aoff);
            #pragma unroll
            for (int nt = 0; nt < 16; nt++) {
                uint32_t boff = (uint32_t)((nt * 8 + bi) * B_STRIDE + ks * 16 + bs * 8) * 2;
                uint32_t bw[2];
                ldm2(bw, bbuf + boff);
                float* d = acc1[h * 16 + nt];
                mma_f16(d, ahi, bw);
                mma_f16(d, alo, bw);
            }
        }
        __syncthreads();   // everyone done reading this buffer
        if (h == 0) {      // prefetch W2 kh0 into buffer 0 (T2)
            cp_tile(sbase + SM_BB0, g_w2h, 256, tid); CP_COMMIT();
        } else {           // prefetch W2 kh1 into buffer 1 (T3)
            cp_tile(sbase + SM_BB1, g_w2h + 128, 256, tid); CP_COMMIT();
        }
    }

    // ---- conversion: t = silu(acc1 + b1) -> fp16 hi/lo into A region ----
    // (GEMM1 A-reads all completed at the sync above; each warp writes own rows)
    {
        int r0 = rb + (lane >> 2), r1 = r0 + 8;
        #pragma unroll
        for (int nt = 0; nt < 32; nt++) {
            int c0 = nt * 8 + 2 * q;
            float t0 = silu_f(acc1[nt][0] + sb1[c0]);
            float t1 = silu_f(acc1[nt][1] + sb1[c0 + 1]);
            float t2 = silu_f(acc1[nt][2] + sb1[c0]);
            float t3 = silu_f(acc1[nt][3] + sb1[c0 + 1]);
            __half h0 = __float2half_rn(t0), h1 = __float2half_rn(t1);
            __half h2 = __float2half_rn(t2), h3 = __float2half_rn(t3);
            int o0 = (r0 * A_STRIDE + c0) * 2;
            int o1 = (r1 * A_STRIDE + c0) * 2;
            *(__half2*)(smem + SM_A_HI + o0) = __halves2half2(h0, h1);
            *(__half2*)(smem + SM_A_LO + o0) =
                __floats2half2_rn(t0 - __half2float(h0), t1 - __half2float(h1));
            *(__half2*)(smem + SM_A_HI + o1) = __halves2half2(h2, h3);
            *(__half2*)(smem + SM_A_LO + o1) =
                __floats2half2_rn(t2 - __half2float(h2), t3 - __half2float(h3));
        }
    }

    // ---- GEMM2: acc2[m16 x n128] over K=256 in two k-halves ----
    float acc2[16][4];
    #pragma unroll
    for (int i = 0; i < 16; i++)
        #pragma unroll
        for (int j = 0; j < 4; j++) acc2[i][j] = 0.f;

    #pragma unroll 1
    for (int kh = 0; kh < 2; kh++) {
        if (kh == 0) { CP_WAIT(1); }  // T2 ready (pending: T3)
        else         { CP_WAIT(0); }  // T3 ready
        __syncthreads();              // + conversion stores visible (kh==0)
        uint32_t bbuf = sbase + ((kh == 0) ? SM_BB0 : SM_BB1);
        #pragma unroll
        for (int ks = 0; ks < 8; ks++) {
            int g = kh * 8 + ks;
            uint32_t ahi[4], alo[4];
            uint32_t aoff = (uint32_t)(arow * A_STRIDE + g * 16 + acolseg) * 2;
            ldm4(ahi, sbase + SM_A_HI + aoff);
            ldm4(alo, sbase + SM_A_LO + aoff);
            #pragma unroll
            for (int nt = 0; nt < 16; nt++) {
                uint32_t boff = (uint32_t)((nt * 8 + bi) * B_STRIDE + ks * 16 + bs * 8) * 2;
                uint32_t bw[2];
                ldm2(bw, bbuf + boff);
                mma_f16(acc2[nt], ahi, bw);
                mma_f16(acc2[nt], alo, bw);
            }
        }
        if (kh == 0) __syncthreads();  // done reading BB0 before next wait's sync
    }

    // ---- epilogue: msg = h_n * (acc2 + b2); atomicAdd into g_agg[center] ----
    {
        int r0 = rb + (lane >> 2), r1 = r0 + 8;
        int ci0 = s_ci[r0], ci1 = s_ci[r1];
        int ni0 = s_ni[r0], ni1 = s_ni[r1];
        const float* hn0 = g_h + (size_t)ni0 * EMBED;
        const float* hn1 = g_h + (size_t)ni1 * EMBED;
        float* ag0 = g_agg + (size_t)ci0 * EMBED;
        float* ag1 = g_agg + (size_t)ci1 * EMBED;
        #pragma unroll
        for (int nt = 0; nt < 16; nt++) {
            int c0 = nt * 8 + 2 * q;
            float2 h0 = *(const float2*)(hn0 + c0);
            float2 h1 = *(const float2*)(hn1 + c0);
            atomicAdd(ag0 + c0,     (acc2[nt][0] + sb2[c0])     * h0.x);
            atomicAdd(ag0 + c0 + 1, (acc2[nt][1] + sb2[c0 + 1]) * h0.y);
            atomicAdd(ag1 + c0,     (acc2[nt][2] + sb2[c0])     * h1.x);
            atomicAdd(ag1 + c0 + 1, (acc2[nt][3] + sb2[c0 + 1]) * h1.y);
        }
    }
}

// ---------------------------------------------------------------------------
// Kernel 3: out = silu(h + agg) @ Wt + bt   (FFMA2 scalar path)
// ---------------------------------------------------------------------------
__global__ __launch_bounds__(256)
void out_kernel(const float* __restrict__ Wt, const float* __restrict__ bt,
                float* __restrict__ out) {
    __shared__ float s_x[32 * EMBED];
    __shared__ float s_w[32 * EMBED];

    int tid = threadIdx.x;
    int n0 = blockIdx.x * 32;

    #pragma unroll
    for (int r = 0; r < 4; r++) {
        int v = tid + 256 * r;
        int e = v >> 5;
        int c = v & 31;
        int row = n0 + e;
        float4 xv = make_float4(0.f, 0.f, 0.f, 0.f);
        if (row < N_NODES) {
            float4 hv = ((const float4*)(g_h + (size_t)row * EMBED))[c];
            float4 av = ((const float4*)(g_agg + (size_t)row * EMBED))[c];
            xv.x = silu_f(hv.x + av.x);
            xv.y = silu_f(hv.y + av.y);
            xv.z = silu_f(hv.z + av.z);
            xv.w = silu_f(hv.w + av.w);
        }
        ((float4*)s_x)[v] = xv;
    }

    int cg = tid & 31;
    int eg = tid >> 5;
    u64t acc[4][2];
    #pragma unroll
    for (int e = 0; e < 4; e++) { acc[e][0] = 0ull; acc[e][1] = 0ull; }

    for (int kc = 0; kc < EMBED; kc += 32) {
        __syncthreads();
        #pragma unroll
        for (int r = 0; r < 4; r++) {
            int v = tid + 256 * r;
            ((float4*)s_w)[v] = ((const float4*)(Wt + (size_t)kc * EMBED))[v];
        }
        __syncthreads();
        #pragma unroll
        for (int k = 0; k < 32; k++) {
            ulonglong2 w2 = ((const ulonglong2*)(s_w + k * EMBED))[cg];
            #pragma unroll
            for (int e = 0; e < 4; e++) {
                float xv = s_x[(eg * 4 + e) * EMBED + kc + k];
                u64t xv2; DUP2(xv2, xv);
                FMA2(acc[e][0], xv2, w2.x, acc[e][0]);
                FMA2(acc[e][1], xv2, w2.y, acc[e][1]);
            }
        }
    }

    float4 btv = ((const float4*)bt)[cg];
    #pragma unroll
    for (int e = 0; e < 4; e++) {
        int row = n0 + eg * 4 + e;
        if (row < N_NODES) {
            float a0, a1, a2, a3;
            UNPK2(a0, a1, acc[e][0]);
            UNPK2(a2, a3, acc[e][1]);
            float4 o;
            o.x = a0 + btv.x;
            o.y = a1 + btv.y;
            o.z = a2 + btv.z;
            o.w = a3 + btv.w;
            ((float4*)(out + (size_t)row * EMBED))[cg] = o;
        }
    }
}

// ---------------------------------------------------------------------------
extern "C" void kernel_launch(void* const* d_in, const int* in_sizes, int n_in,
                              void* d_out, int out_size) {
    const float* node  = (const float*)d_in[0];
    const float* eemb  = (const float*)d_in[1];
    const int*   eidx  = (const int*)  d_in[2];
    const float* gamma = (const float*)d_in[3];
    const float* beta  = (const float*)d_in[4];
    const float* W1    = (const float*)d_in[5];
    const float* b1    = (const float*)d_in[6];
    const float* W2    = (const float*)d_in[7];
    const float* b2    = (const float*)d_in[8];
    const float* Wt    = (const float*)d_in[9];
    const float* bt    = (const float*)d_in[10];
    float* out = (float*)d_out;

    cudaFuncSetAttribute(edge_kernel, cudaFuncAttributeMaxDynamicSharedMemorySize,
                         EDGE_SMEM);

    prep_kernel<<<128, 256>>>(W1, W2);
    ln_kernel<<<(N_NODES + 7) / 8, 256>>>(node, gamma, beta);
    edge_kernel<<<N_EDGES / TE, ETH, EDGE_SMEM>>>(eemb, eidx, b1, b2);
    out_kernel<<<(N_NODES + 31) / 32, 256>>>(Wt, bt, out);
}

// round 7
// speedup vs baseline: 3.7886x; 2.7885x over previous
#include <cuda_runtime.h>
#include <cuda_fp16.h>
#include <cstdint>

#define N_NODES 50000
#define EMBED 128
#define HIDDEN 256
#define N_EDGES 640000
#define LN_EPS 1e-5f

typedef unsigned long long u64t;

// ---------------- FFMA2 helpers (out_kernel) ----------------
#define FMA2(d, a, b, c) \
    asm("fma.rn.f32x2 %0, %1, %2, %3;" : "=l"(d) : "l"(a), "l"(b), "l"(c))
#define DUP2(d, x) \
    asm("mov.b64 %0, {%1, %1};" : "=l"(d) : "f"(x))
#define UNPK2(lo, hi, p) \
    asm("mov.b64 {%0, %1}, %2;" : "=f"(lo), "=f"(hi) : "l"(p))

// ---------------- warp MMA / cp.async helpers (sm_80-class) ----------------
__device__ __forceinline__ uint32_t smem_u32(const void* p) {
    uint32_t a;
    asm("{ .reg .u64 t; cvta.to.shared.u64 t, %1; cvt.u32.u64 %0, t; }"
        : "=r"(a) : "l"(p));
    return a;
}
__device__ __forceinline__ void mma_f16(float* d, const uint32_t* a, const uint32_t* b) {
    asm volatile(
        "mma.sync.aligned.m16n8k16.row.col.f32.f16.f16.f32 "
        "{%0,%1,%2,%3}, {%4,%5,%6,%7}, {%8,%9}, {%0,%1,%2,%3};"
        : "+f"(d[0]), "+f"(d[1]), "+f"(d[2]), "+f"(d[3])
        : "r"(a[0]), "r"(a[1]), "r"(a[2]), "r"(a[3]), "r"(b[0]), "r"(b[1]));
}
__device__ __forceinline__ void ldm4(uint32_t* r, uint32_t addr) {
    asm volatile("ldmatrix.sync.aligned.m8n8.x4.shared.b16 {%0,%1,%2,%3}, [%4];"
                 : "=r"(r[0]), "=r"(r[1]), "=r"(r[2]), "=r"(r[3]) : "r"(addr));
}
__device__ __forceinline__ void ldm2(uint32_t* r, uint32_t addr) {
    asm volatile("ldmatrix.sync.aligned.m8n8.x2.shared.b16 {%0,%1}, [%2];"
                 : "=r"(r[0]), "=r"(r[1]) : "r"(addr));
}
__device__ __forceinline__ void cpa16(uint32_t dst, const void* src) {
    asm volatile("cp.async.cg.shared.global [%0], [%1], 16;" :: "r"(dst), "l"(src));
}
#define CP_COMMIT() asm volatile("cp.async.commit_group;" ::: "memory")
#define CP_WAIT(n)  asm volatile("cp.async.wait_group %0;" :: "n"(n) : "memory")

__device__ __forceinline__ float silu_f(float x) {
    return __fdividef(x, 1.0f + __expf(-x));
}

// ---------------- device scratch ----------------
__device__ float g_h[N_NODES * EMBED];
__device__ float g_agg[N_NODES * EMBED];
// fp16 transposed weight images: w1 [n=256][k=128], w2 [n=128][kk=256]
__device__ __align__(16) __half g_w1h[32768];
__device__ __align__(16) __half g_w2h[32768];

// ---------------------------------------------------------------------------
// Prep: W1/W2 -> fp16 transposed images
// ---------------------------------------------------------------------------
__global__ void prep_kernel(const float* __restrict__ W1, const float* __restrict__ W2) {
    int idx = blockIdx.x * blockDim.x + threadIdx.x;
    if (idx >= 32768) return;
    {   // W1 [k=128][n=256] -> [n][k]
        int k = idx >> 8, n = idx & 255;
        g_w1h[n * 128 + k] = __float2half_rn(W1[idx]);
    }
    {   // W2 [kk=256][n=128] -> [n][kk]
        int kk = idx >> 7, n = idx & 127;
        g_w2h[n * 256 + kk] = __float2half_rn(W2[idx]);
    }
}

// ---------------------------------------------------------------------------
// Kernel 1: LayerNorm (warp per row) + zero g_agg
// ---------------------------------------------------------------------------
__global__ void ln_kernel(const float* __restrict__ x,
                          const float* __restrict__ gamma,
                          const float* __restrict__ beta) {
    int warp = (blockIdx.x * blockDim.x + threadIdx.x) >> 5;
    int lane = threadIdx.x & 31;
    if (warp >= N_NODES) return;

    const float4* row = (const float4*)(x + (size_t)warp * EMBED);
    float4 v = row[lane];
    float s  = v.x + v.y + v.z + v.w;
    float ss = v.x * v.x + v.y * v.y + v.z * v.z + v.w * v.w;
    #pragma unroll
    for (int o = 16; o; o >>= 1) {
        s  += __shfl_xor_sync(0xFFFFFFFFu, s,  o);
        ss += __shfl_xor_sync(0xFFFFFFFFu, ss, o);
    }
    const float inv_d = 1.0f / (float)EMBED;
    float mu  = s * inv_d;
    float var = ss * inv_d - mu * mu;
    float inv = rsqrtf(var + LN_EPS);

    float4 g = ((const float4*)gamma)[lane];
    float4 b = ((const float4*)beta)[lane];
    float4 o4;
    o4.x = (v.x - mu) * inv * g.x + b.x;
    o4.y = (v.y - mu) * inv * g.y + b.y;
    o4.z = (v.z - mu) * inv * g.z + b.z;
    o4.w = (v.w - mu) * inv * g.w + b.w;
    ((float4*)(g_h + (size_t)warp * EMBED))[lane] = o4;
    ((float4*)(g_agg + (size_t)warp * EMBED))[lane] = make_float4(0.f, 0.f, 0.f, 0.f);
}

// ---------------------------------------------------------------------------
// Kernel 2: fp16 mma.sync edge MLP. 128 edges/CTA, 8 warps, 2 CTAs/SM.
// A single fp16 plane [128 rows x 256 cols]; GEMM1 reads cols 0..127,
// conversion h0 writes t[0..127] -> cols 128..255, h1 -> cols 0..127.
// GEMM2 phase0 pairs A cols 128..255 with W2 rows 0..127, phase1 the rest.
// ---------------------------------------------------------------------------
#define TE 128
#define ETH 256
#define A_STRIDE 264   // halves; 528B rows -> 16B-rotating, ldmatrix conflict-free
#define B_STRIDE 136   // halves; 272B rows

#define SM_CI   0
#define SM_NI   512
#define SM_B1   1024
#define SM_B2   2048
#define SM_A    2560
#define SM_B    (SM_A + 128 * A_STRIDE * 2)   // 70144
#define EDGE_SMEM (SM_B + 128 * B_STRIDE * 2) // 104960  -> 2 CTAs/SM

// async copy of a 128x128-half tile into padded B buffer (8 x 16B per thread)
__device__ __forceinline__ void cp_tile(uint32_t sdst,
                                        const __half* __restrict__ src,
                                        int src_stride_halves, int tid) {
    #pragma unroll
    for (int i = tid; i < 2048; i += ETH) {
        int r = i >> 4, c = i & 15;
        cpa16(sdst + r * (B_STRIDE * 2) + c * 16,
              src + r * src_stride_halves + c * 8);
    }
}

__global__ __launch_bounds__(ETH, 2)
void edge_kernel(const float* __restrict__ eemb,
                 const int* __restrict__ eidx,
                 const float* __restrict__ b1g,
                 const float* __restrict__ b2g) {
    extern __shared__ char smem[];
    uint32_t sbase = smem_u32(smem);
    int tid = threadIdx.x, wid = tid >> 5, lane = tid & 31;
    int e0 = blockIdx.x * TE;

    int*   s_ci = (int*)(smem + SM_CI);
    int*   s_ni = (int*)(smem + SM_NI);
    float* sb1  = (float*)(smem + SM_B1);
    float* sb2  = (float*)(smem + SM_B2);

    // prefetch W1 n-half0 (overlaps gather below)
    cp_tile(sbase + SM_B, g_w1h, 128, tid); CP_COMMIT();

    if (tid < 128) {
        s_ci[tid] = eidx[e0 + tid];
        s_ni[tid] = eidx[N_EDGES + e0 + tid];
    }
    sb1[tid] = b1g[tid];
    if (tid < 128) sb2[tid] = b2g[tid];
    __syncthreads();

    // ---- gather: A1 = fp16(silu(e + h_c + h_n)) into A cols 0..127 ----
    #pragma unroll
    for (int it = 0; it < 16; it++) {
        int v = tid + ETH * it;       // 0..4095
        int m = v >> 5, c = v & 31;   // edge row, float4 col (k = 4c..4c+3)
        float4 ee = ((const float4*)(eemb + (size_t)(e0 + m) * EMBED))[c];
        float4 hc = ((const float4*)(g_h + (size_t)s_ci[m] * EMBED))[c];
        float4 hn = ((const float4*)(g_h + (size_t)s_ni[m] * EMBED))[c];
        float s0 = silu_f(ee.x + hc.x + hn.x);
        float s1 = silu_f(ee.y + hc.y + hn.y);
        float s2 = silu_f(ee.z + hc.z + hn.z);
        float s3 = silu_f(ee.w + hc.w + hn.w);
        __half2 p0 = __floats2half2_rn(s0, s1);
        __half2 p1 = __floats2half2_rn(s2, s3);
        int off = (m * A_STRIDE + 4 * c) * 2;
        *(__half2*)(smem + SM_A + off)     = p0;
        *(__half2*)(smem + SM_A + off + 4) = p1;
    }

    int rb = wid * 16;
    int ai = lane & 7, as_ = lane >> 3;
    int arow = rb + ai + (as_ & 1) * 8;
    int acolseg = (as_ >> 1) * 8;
    int bi = lane & 7, bs = (lane >> 3) & 1;
    int q = lane & 3;
    int r0 = rb + (lane >> 2), r1 = r0 + 8;

    // ================= GEMM1 (two n-halves, acc regs reused) =================
    #pragma unroll 1
    for (int h = 0; h < 2; h++) {
        CP_WAIT(0);
        __syncthreads();   // B tile ready; prior readers done

        float acc[16][4];
        #pragma unroll
        for (int i = 0; i < 16; i++)
            #pragma unroll
            for (int j = 0; j < 4; j++) acc[i][j] = 0.f;

        #pragma unroll
        for (int ks = 0; ks < 8; ks++) {
            uint32_t a4[4];
            uint32_t aoff = (uint32_t)(arow * A_STRIDE + ks * 16 + acolseg) * 2;
            ldm4(a4, sbase + SM_A + aoff);
            #pragma unroll
            for (int nt = 0; nt < 16; nt++) {
                uint32_t boff = (uint32_t)((nt * 8 + bi) * B_STRIDE + ks * 16 + bs * 8) * 2;
                uint32_t bw[2];
                ldm2(bw, sbase + SM_B + boff);
                mma_f16(acc[nt], a4, bw);
            }
        }
        __syncthreads();   // all warps done reading B tile

        // prefetch next B: h0 -> W1 n-half1 ; h1 -> W2 k-rows 0..127
        if (h == 0) { cp_tile(sbase + SM_B, g_w1h + 16384, 128, tid); CP_COMMIT(); }
        else        { cp_tile(sbase + SM_B, g_w2h,         256, tid); CP_COMMIT(); }

        // conversion (overlaps copy): t = silu(acc + b1) -> fp16 into A
        // h0: t cols 0..127  -> A cols 128..255 (A1 cols 0..127 still live)
        // h1: t cols 128..255-> A cols 0..127   (own-row writes, warp-private)
        int dbase = (h == 0) ? 128 : 0;
        #pragma unroll
        for (int nt = 0; nt < 16; nt++) {
            int c0 = nt * 8 + 2 * q;             // 0..127 within half
            int gc = h * 128 + c0;               // global t col
            float t0 = silu_f(acc[nt][0] + sb1[gc]);
            float t1 = silu_f(acc[nt][1] + sb1[gc + 1]);
            float t2 = silu_f(acc[nt][2] + sb1[gc]);
            float t3 = silu_f(acc[nt][3] + sb1[gc + 1]);
            int o0 = (r0 * A_STRIDE + dbase + c0) * 2;
            int o1 = (r1 * A_STRIDE + dbase + c0) * 2;
            *(__half2*)(smem + SM_A + o0) = __floats2half2_rn(t0, t1);
            *(__half2*)(smem + SM_A + o1) = __floats2half2_rn(t2, t3);
        }
    }

    // ================= GEMM2 (two k-phases into persistent acc2) =============
    float acc2[16][4];
    #pragma unroll
    for (int i = 0; i < 16; i++)
        #pragma unroll
        for (int j = 0; j < 4; j++) acc2[i][j] = 0.f;

    #pragma unroll 1
    for (int ph = 0; ph < 2; ph++) {
        CP_WAIT(0);
        __syncthreads();   // W2 tile ready (+ conversion stores visible CTA-wide)

        // ph0: A cols 128..255 (t 0..127) vs W2 rows 0..127
        // ph1: A cols 0..127   (t 128..255) vs W2 rows 128..255
        int abase = (ph == 0) ? 128 : 0;
        #pragma unroll
        for (int ks = 0; ks < 8; ks++) {
            uint32_t a4[4];
            uint32_t aoff = (uint32_t)(arow * A_STRIDE + abase + ks * 16 + acolseg) * 2;
            ldm4(a4, sbase + SM_A + aoff);
            #pragma unroll
            for (int nt = 0; nt < 16; nt++) {
                uint32_t boff = (uint32_t)((nt * 8 + bi) * B_STRIDE + ks * 16 + bs * 8) * 2;
                uint32_t bw[2];
                ldm2(bw, sbase + SM_B + boff);
                mma_f16(acc2[nt], a4, bw);
            }
        }
        if (ph == 0) {
            __syncthreads();   // done reading W2 phase-0 tile
            cp_tile(sbase + SM_B, g_w2h + 128, 256, tid); CP_COMMIT();
        }
    }

    // ---- epilogue: msg = h_n * (acc2 + b2); atomicAdd into g_agg[center] ----
    {
        int ci0 = s_ci[r0], ci1 = s_ci[r1];
        int ni0 = s_ni[r0], ni1 = s_ni[r1];
        const float* hn0 = g_h + (size_t)ni0 * EMBED;
        const float* hn1 = g_h + (size_t)ni1 * EMBED;
        float* ag0 = g_agg + (size_t)ci0 * EMBED;
        float* ag1 = g_agg + (size_t)ci1 * EMBED;
        #pragma unroll
        for (int nt = 0; nt < 16; nt++) {
            int c0 = nt * 8 + 2 * q;
            float2 h0 = *(const float2*)(hn0 + c0);
            float2 h1 = *(const float2*)(hn1 + c0);
            atomicAdd(ag0 + c0,     (acc2[nt][0] + sb2[c0])     * h0.x);
            atomicAdd(ag0 + c0 + 1, (acc2[nt][1] + sb2[c0 + 1]) * h0.y);
            atomicAdd(ag1 + c0,     (acc2[nt][2] + sb2[c0])     * h1.x);
            atomicAdd(ag1 + c0 + 1, (acc2[nt][3] + sb2[c0 + 1]) * h1.y);
        }
    }
}

// ---------------------------------------------------------------------------
// Kernel 3: out = silu(h + agg) @ Wt + bt   (FFMA2 scalar path)
// ---------------------------------------------------------------------------
__global__ __launch_bounds__(256)
void out_kernel(const float* __restrict__ Wt, const float* __restrict__ bt,
                float* __restrict__ out) {
    __shared__ float s_x[32 * EMBED];
    __shared__ float s_w[32 * EMBED];

    int tid = threadIdx.x;
    int n0 = blockIdx.x * 32;

    #pragma unroll
    for (int r = 0; r < 4; r++) {
        int v = tid + 256 * r;
        int e = v >> 5;
        int c = v & 31;
        int row = n0 + e;
        float4 xv = make_float4(0.f, 0.f, 0.f, 0.f);
        if (row < N_NODES) {
            float4 hv = ((const float4*)(g_h + (size_t)row * EMBED))[c];
            float4 av = ((const float4*)(g_agg + (size_t)row * EMBED))[c];
            xv.x = silu_f(hv.x + av.x);
            xv.y = silu_f(hv.y + av.y);
            xv.z = silu_f(hv.z + av.z);
            xv.w = silu_f(hv.w + av.w);
        }
        ((float4*)s_x)[v] = xv;
    }

    int cg = tid & 31;
    int eg = tid >> 5;
    u64t acc[4][2];
    #pragma unroll
    for (int e = 0; e < 4; e++) { acc[e][0] = 0ull; acc[e][1] = 0ull; }

    for (int kc = 0; kc < EMBED; kc += 32) {
        __syncthreads();
        #pragma unroll
        for (int r = 0; r < 4; r++) {
            int v = tid + 256 * r;
            ((float4*)s_w)[v] = ((const float4*)(Wt + (size_t)kc * EMBED))[v];
        }
        __syncthreads();
        #pragma unroll
        for (int k = 0; k < 32; k++) {
            ulonglong2 w2 = ((const ulonglong2*)(s_w + k * EMBED))[cg];
            #pragma unroll
            for (int e = 0; e < 4; e++) {
                float xv = s_x[(eg * 4 + e) * EMBED + kc + k];
                u64t xv2; DUP2(xv2, xv);
                FMA2(acc[e][0], xv2, w2.x, acc[e][0]);
                FMA2(acc[e][1], xv2, w2.y, acc[e][1]);
            }
        }
    }

    float4 btv = ((const float4*)bt)[cg];
    #pragma unroll
    for (int e = 0; e < 4; e++) {
        int row = n0 + eg * 4 + e;
        if (row < N_NODES) {
            float a0, a1, a2, a3;
            UNPK2(a0, a1, acc[e][0]);
            UNPK2(a2, a3, acc[e][1]);
            float4 o;
            o.x = a0 + btv.x;
            o.y = a1 + btv.y;
            o.z = a2 + btv.z;
            o.w = a3 + btv.w;
            ((float4*)(out + (size_t)row * EMBED))[cg] = o;
        }
    }
}

// ---------------------------------------------------------------------------
extern "C" void kernel_launch(void* const* d_in, const int* in_sizes, int n_in,
                              void* d_out, int out_size) {
    const float* node  = (const float*)d_in[0];
    const float* eemb  = (const float*)d_in[1];
    const int*   eidx  = (const int*)  d_in[2];
    const float* gamma = (const float*)d_in[3];
    const float* beta  = (const float*)d_in[4];
    const float* W1    = (const float*)d_in[5];
    const float* b1    = (const float*)d_in[6];
    const float* W2    = (const float*)d_in[7];
    const float* b2    = (const float*)d_in[8];
    const float* Wt    = (const float*)d_in[9];
    const float* bt    = (const float*)d_in[10];
    float* out = (float*)d_out;

    cudaFuncSetAttribute(edge_kernel, cudaFuncAttributeMaxDynamicSharedMemorySize,
                         EDGE_SMEM);

    prep_kernel<<<128, 256>>>(W1, W2);
    ln_kernel<<<(N_NODES + 7) / 8, 256>>>(node, gamma, beta);
    edge_kernel<<<N_EDGES / TE, ETH, EDGE_SMEM>>>(eemb, eidx, b1, b2);
    out_kernel<<<(N_NODES + 31) / 32, 256>>>(Wt, bt, out);
}

// round 8
// speedup vs baseline: 3.9320x; 1.0379x over previous
#include <cuda_runtime.h>
#include <cuda_fp16.h>
#include <cstdint>

#define N_NODES 50000
#define EMBED 128
#define HIDDEN 256
#define N_EDGES 640000
#define LN_EPS 1e-5f

// ---------------- warp MMA / cp.async helpers (sm_80-class) ----------------
__device__ __forceinline__ uint32_t smem_u32(const void* p) {
    uint32_t a;
    asm("{ .reg .u64 t; cvta.to.shared.u64 t, %1; cvt.u32.u64 %0, t; }"
        : "=r"(a) : "l"(p));
    return a;
}
__device__ __forceinline__ void mma_f16(float* d, const uint32_t* a, const uint32_t* b) {
    asm volatile(
        "mma.sync.aligned.m16n8k16.row.col.f32.f16.f16.f32 "
        "{%0,%1,%2,%3}, {%4,%5,%6,%7}, {%8,%9}, {%0,%1,%2,%3};"
        : "+f"(d[0]), "+f"(d[1]), "+f"(d[2]), "+f"(d[3])
        : "r"(a[0]), "r"(a[1]), "r"(a[2]), "r"(a[3]), "r"(b[0]), "r"(b[1]));
}
__device__ __forceinline__ void ldm4(uint32_t* r, uint32_t addr) {
    asm volatile("ldmatrix.sync.aligned.m8n8.x4.shared.b16 {%0,%1,%2,%3}, [%4];"
                 : "=r"(r[0]), "=r"(r[1]), "=r"(r[2]), "=r"(r[3]) : "r"(addr));
}
__device__ __forceinline__ void ldm2(uint32_t* r, uint32_t addr) {
    asm volatile("ldmatrix.sync.aligned.m8n8.x2.shared.b16 {%0,%1}, [%2];"
                 : "=r"(r[0]), "=r"(r[1]) : "r"(addr));
}
__device__ __forceinline__ void cpa16(uint32_t dst, const void* src) {
    asm volatile("cp.async.cg.shared.global [%0], [%1], 16;" :: "r"(dst), "l"(src));
}
#define CP_COMMIT() asm volatile("cp.async.commit_group;" ::: "memory")
#define CP_WAIT(n)  asm volatile("cp.async.wait_group %0;" :: "n"(n) : "memory")

__device__ __forceinline__ float silu_f(float x) {
    return __fdividef(x, 1.0f + __expf(-x));
}

// ---------------- device scratch ----------------
__device__ float g_h[N_NODES * EMBED];
__device__ float g_agg[N_NODES * EMBED];
// fp16 transposed weight images: w1 [n=256][k=128], w2 [n=128][kk=256], wt [n=128][k=128]
__device__ __align__(16) __half g_w1h[32768];
__device__ __align__(16) __half g_w2h[32768];
__device__ __align__(16) __half g_wth[16384];

// ---------------------------------------------------------------------------
// Prep: W1/W2/Wt -> fp16 transposed images
// ---------------------------------------------------------------------------
__global__ void prep_kernel(const float* __restrict__ W1, const float* __restrict__ W2,
                            const float* __restrict__ Wt) {
    int idx = blockIdx.x * blockDim.x + threadIdx.x;
    if (idx >= 32768) return;
    {   // W1 [k=128][n=256] -> [n][k]
        int k = idx >> 8, n = idx & 255;
        g_w1h[n * 128 + k] = __float2half_rn(W1[idx]);
    }
    {   // W2 [kk=256][n=128] -> [n][kk]
        int kk = idx >> 7, n = idx & 127;
        g_w2h[n * 256 + kk] = __float2half_rn(W2[idx]);
    }
    if (idx < 16384) {   // Wt [k=128][n=128] -> [n][k]
        int k = idx >> 7, n = idx & 127;
        g_wth[n * 128 + k] = __float2half_rn(Wt[idx]);
    }
}

// ---------------------------------------------------------------------------
// Kernel 1: LayerNorm (warp per row) + zero g_agg
// ---------------------------------------------------------------------------
__global__ void ln_kernel(const float* __restrict__ x,
                          const float* __restrict__ gamma,
                          const float* __restrict__ beta) {
    int warp = (blockIdx.x * blockDim.x + threadIdx.x) >> 5;
    int lane = threadIdx.x & 31;
    if (warp >= N_NODES) return;

    const float4* row = (const float4*)(x + (size_t)warp * EMBED);
    float4 v = row[lane];
    float s  = v.x + v.y + v.z + v.w;
    float ss = v.x * v.x + v.y * v.y + v.z * v.z + v.w * v.w;
    #pragma unroll
    for (int o = 16; o; o >>= 1) {
        s  += __shfl_xor_sync(0xFFFFFFFFu, s,  o);
        ss += __shfl_xor_sync(0xFFFFFFFFu, ss, o);
    }
    const float inv_d = 1.0f / (float)EMBED;
    float mu  = s * inv_d;
    float var = ss * inv_d - mu * mu;
    float inv = rsqrtf(var + LN_EPS);

    float4 g = ((const float4*)gamma)[lane];
    float4 b = ((const float4*)beta)[lane];
    float4 o4;
    o4.x = (v.x - mu) * inv * g.x + b.x;
    o4.y = (v.y - mu) * inv * g.y + b.y;
    o4.z = (v.z - mu) * inv * g.z + b.z;
    o4.w = (v.w - mu) * inv * g.w + b.w;
    ((float4*)(g_h + (size_t)warp * EMBED))[lane] = o4;
    ((float4*)(g_agg + (size_t)warp * EMBED))[lane] = make_float4(0.f, 0.f, 0.f, 0.f);
}

// ---------------------------------------------------------------------------
// Kernel 2: fp16 mma.sync edge MLP. 128 edges/CTA, 8 warps, 2 CTAs/SM.
// (unchanged from R7 — at HMMA issue floor)
// ---------------------------------------------------------------------------
#define TE 128
#define ETH 256
#define A_STRIDE 264   // halves; 528B rows -> 16B-rotating, ldmatrix conflict-free
#define B_STRIDE 136   // halves; 272B rows

#define SM_CI   0
#define SM_NI   512
#define SM_B1   1024
#define SM_B2   2048
#define SM_A    2560
#define SM_B    (SM_A + 128 * A_STRIDE * 2)   // 70144
#define EDGE_SMEM (SM_B + 128 * B_STRIDE * 2) // 104960  -> 2 CTAs/SM

__device__ __forceinline__ void cp_tile(uint32_t sdst,
                                        const __half* __restrict__ src,
                                        int src_stride_halves, int tid) {
    #pragma unroll
    for (int i = tid; i < 2048; i += ETH) {
        int r = i >> 4, c = i & 15;
        cpa16(sdst + r * (B_STRIDE * 2) + c * 16,
              src + r * src_stride_halves + c * 8);
    }
}

__global__ __launch_bounds__(ETH, 2)
void edge_kernel(const float* __restrict__ eemb,
                 const int* __restrict__ eidx,
                 const float* __restrict__ b1g,
                 const float* __restrict__ b2g) {
    extern __shared__ char smem[];
    uint32_t sbase = smem_u32(smem);
    int tid = threadIdx.x, wid = tid >> 5, lane = tid & 31;
    int e0 = blockIdx.x * TE;

    int*   s_ci = (int*)(smem + SM_CI);
    int*   s_ni = (int*)(smem + SM_NI);
    float* sb1  = (float*)(smem + SM_B1);
    float* sb2  = (float*)(smem + SM_B2);

    cp_tile(sbase + SM_B, g_w1h, 128, tid); CP_COMMIT();

    if (tid < 128) {
        s_ci[tid] = eidx[e0 + tid];
        s_ni[tid] = eidx[N_EDGES + e0 + tid];
    }
    sb1[tid] = b1g[tid];
    if (tid < 128) sb2[tid] = b2g[tid];
    __syncthreads();

    #pragma unroll
    for (int it = 0; it < 16; it++) {
        int v = tid + ETH * it;
        int m = v >> 5, c = v & 31;
        float4 ee = ((const float4*)(eemb + (size_t)(e0 + m) * EMBED))[c];
        float4 hc = ((const float4*)(g_h + (size_t)s_ci[m] * EMBED))[c];
        float4 hn = ((const float4*)(g_h + (size_t)s_ni[m] * EMBED))[c];
        float s0 = silu_f(ee.x + hc.x + hn.x);
        float s1 = silu_f(ee.y + hc.y + hn.y);
        float s2 = silu_f(ee.z + hc.z + hn.z);
        float s3 = silu_f(ee.w + hc.w + hn.w);
        __half2 p0 = __floats2half2_rn(s0, s1);
        __half2 p1 = __floats2half2_rn(s2, s3);
        int off = (m * A_STRIDE + 4 * c) * 2;
        *(__half2*)(smem + SM_A + off)     = p0;
        *(__half2*)(smem + SM_A + off + 4) = p1;
    }

    int rb = wid * 16;
    int ai = lane & 7, as_ = lane >> 3;
    int arow = rb + ai + (as_ & 1) * 8;
    int acolseg = (as_ >> 1) * 8;
    int bi = lane & 7, bs = (lane >> 3) & 1;
    int q = lane & 3;
    int r0 = rb + (lane >> 2), r1 = r0 + 8;

    // ================= GEMM1 (two n-halves) =================
    #pragma unroll 1
    for (int h = 0; h < 2; h++) {
        CP_WAIT(0);
        __syncthreads();

        float acc[16][4];
        #pragma unroll
        for (int i = 0; i < 16; i++)
            #pragma unroll
            for (int j = 0; j < 4; j++) acc[i][j] = 0.f;

        #pragma unroll
        for (int ks = 0; ks < 8; ks++) {
            uint32_t a4[4];
            uint32_t aoff = (uint32_t)(arow * A_STRIDE + ks * 16 + acolseg) * 2;
            ldm4(a4, sbase + SM_A + aoff);
            #pragma unroll
            for (int nt = 0; nt < 16; nt++) {
                uint32_t boff = (uint32_t)((nt * 8 + bi) * B_STRIDE + ks * 16 + bs * 8) * 2;
                uint32_t bw[2];
                ldm2(bw, sbase + SM_B + boff);
                mma_f16(acc[nt], a4, bw);
            }
        }
        __syncthreads();

        if (h == 0) { cp_tile(sbase + SM_B, g_w1h + 16384, 128, tid); CP_COMMIT(); }
        else        { cp_tile(sbase + SM_B, g_w2h,         256, tid); CP_COMMIT(); }

        int dbase = (h == 0) ? 128 : 0;
        #pragma unroll
        for (int nt = 0; nt < 16; nt++) {
            int c0 = nt * 8 + 2 * q;
            int gc = h * 128 + c0;
            float t0 = silu_f(acc[nt][0] + sb1[gc]);
            float t1 = silu_f(acc[nt][1] + sb1[gc + 1]);
            float t2 = silu_f(acc[nt][2] + sb1[gc]);
            float t3 = silu_f(acc[nt][3] + sb1[gc + 1]);
            int o0 = (r0 * A_STRIDE + dbase + c0) * 2;
            int o1 = (r1 * A_STRIDE + dbase + c0) * 2;
            *(__half2*)(smem + SM_A + o0) = __floats2half2_rn(t0, t1);
            *(__half2*)(smem + SM_A + o1) = __floats2half2_rn(t2, t3);
        }
    }

    // ================= GEMM2 (two k-phases) =============
    float acc2[16][4];
    #pragma unroll
    for (int i = 0; i < 16; i++)
        #pragma unroll
        for (int j = 0; j < 4; j++) acc2[i][j] = 0.f;

    #pragma unroll 1
    for (int ph = 0; ph < 2; ph++) {
        CP_WAIT(0);
        __syncthreads();

        int abase = (ph == 0) ? 128 : 0;
        #pragma unroll
        for (int ks = 0; ks < 8; ks++) {
            uint32_t a4[4];
            uint32_t aoff = (uint32_t)(arow * A_STRIDE + abase + ks * 16 + acolseg) * 2;
            ldm4(a4, sbase + SM_A + aoff);
            #pragma unroll
            for (int nt = 0; nt < 16; nt++) {
                uint32_t boff = (uint32_t)((nt * 8 + bi) * B_STRIDE + ks * 16 + bs * 8) * 2;
                uint32_t bw[2];
                ldm2(bw, sbase + SM_B + boff);
                mma_f16(acc2[nt], a4, bw);
            }
        }
        if (ph == 0) {
            __syncthreads();
            cp_tile(sbase + SM_B, g_w2h + 128, 256, tid); CP_COMMIT();
        }
    }

    // ---- epilogue ----
    {
        int ci0 = s_ci[r0], ci1 = s_ci[r1];
        int ni0 = s_ni[r0], ni1 = s_ni[r1];
        const float* hn0 = g_h + (size_t)ni0 * EMBED;
        const float* hn1 = g_h + (size_t)ni1 * EMBED;
        float* ag0 = g_agg + (size_t)ci0 * EMBED;
        float* ag1 = g_agg + (size_t)ci1 * EMBED;
        #pragma unroll
        for (int nt = 0; nt < 16; nt++) {
            int c0 = nt * 8 + 2 * q;
            float2 h0 = *(const float2*)(hn0 + c0);
            float2 h1 = *(const float2*)(hn1 + c0);
            atomicAdd(ag0 + c0,     (acc2[nt][0] + sb2[c0])     * h0.x);
            atomicAdd(ag0 + c0 + 1, (acc2[nt][1] + sb2[c0 + 1]) * h0.y);
            atomicAdd(ag1 + c0,     (acc2[nt][2] + sb2[c0])     * h1.x);
            atomicAdd(ag1 + c0 + 1, (acc2[nt][3] + sb2[c0 + 1]) * h1.y);
        }
    }
}

// ---------------------------------------------------------------------------
// Kernel 3 (NEW): out = silu(h + agg) @ Wt + bt  via fp16 mma.sync
// 128 node rows per CTA, 8 warps, ~70KB smem -> 2+ CTAs/SM
// ---------------------------------------------------------------------------
#define OSM_BT  0
#define OSM_A   512
#define OSM_B   (OSM_A + 128 * B_STRIDE * 2)    // 35328
#define OUT_SMEM (OSM_B + 128 * B_STRIDE * 2)   // 70144

__global__ __launch_bounds__(256, 2)
void out_kernel(const float* __restrict__ btg, float* __restrict__ out) {
    extern __shared__ char smem[];
    uint32_t sbase = smem_u32(smem);
    int tid = threadIdx.x, wid = tid >> 5, lane = tid & 31;
    int n0 = blockIdx.x * 128;

    float* sbt = (float*)(smem + OSM_BT);

    // prefetch Wt^T tile (overlaps gather)
    cp_tile(sbase + OSM_B, g_wth, 128, tid); CP_COMMIT();
    if (tid < 128) sbt[tid] = btg[tid];

    // ---- gather: A = fp16(silu(h + agg)) [128 rows x 128 cols] ----
    #pragma unroll
    for (int it = 0; it < 16; it++) {
        int v = tid + 256 * it;       // 0..4095
        int m = v >> 5, c = v & 31;
        int row = n0 + m;
        float s0 = 0.f, s1 = 0.f, s2 = 0.f, s3 = 0.f;
        if (row < N_NODES) {
            float4 hv = ((const float4*)(g_h + (size_t)row * EMBED))[c];
            float4 av = ((const float4*)(g_agg + (size_t)row * EMBED))[c];
            s0 = silu_f(hv.x + av.x);
            s1 = silu_f(hv.y + av.y);
            s2 = silu_f(hv.z + av.z);
            s3 = silu_f(hv.w + av.w);
        }
        int off = (m * B_STRIDE + 4 * c) * 2;
        *(__half2*)(smem + OSM_A + off)     = __floats2half2_rn(s0, s1);
        *(__half2*)(smem + OSM_A + off + 4) = __floats2half2_rn(s2, s3);
    }

    CP_WAIT(0);
    __syncthreads();

    int rb = wid * 16;
    int ai = lane & 7, as_ = lane >> 3;
    int arow = rb + ai + (as_ & 1) * 8;
    int acolseg = (as_ >> 1) * 8;
    int bi = lane & 7, bs = (lane >> 3) & 1;
    int q = lane & 3;
    int r0 = rb + (lane >> 2), r1 = r0 + 8;

    float acc[16][4];
    #pragma unroll
    for (int i = 0; i < 16; i++)
        #pragma unroll
        for (int j = 0; j < 4; j++) acc[i][j] = 0.f;

    #pragma unroll
    for (int ks = 0; ks < 8; ks++) {
        uint32_t a4[4];
        uint32_t aoff = (uint32_t)(arow * B_STRIDE + ks * 16 + acolseg) * 2;
        ldm4(a4, sbase + OSM_A + aoff);
        #pragma unroll
        for (int nt = 0; nt < 16; nt++) {
            uint32_t boff = (uint32_t)((nt * 8 + bi) * B_STRIDE + ks * 16 + bs * 8) * 2;
            uint32_t bw[2];
            ldm2(bw, sbase + OSM_B + boff);
            mma_f16(acc[nt], a4, bw);
        }
    }

    // ---- epilogue: out[row][c] = acc + bt[c] ----
    int row0 = n0 + r0, row1 = n0 + r1;
    #pragma unroll
    for (int nt = 0; nt < 16; nt++) {
        int c0 = nt * 8 + 2 * q;
        float2 b2 = *(const float2*)(sbt + c0);
        if (row0 < N_NODES) {
            float2 o0 = make_float2(acc[nt][0] + b2.x, acc[nt][1] + b2.y);
            *(float2*)(out + (size_t)row0 * EMBED + c0) = o0;
        }
        if (row1 < N_NODES) {
            float2 o1 = make_float2(acc[nt][2] + b2.x, acc[nt][3] + b2.y);
            *(float2*)(out + (size_t)row1 * EMBED + c0) = o1;
        }
    }
}

// ---------------------------------------------------------------------------
extern "C" void kernel_launch(void* const* d_in, const int* in_sizes, int n_in,
                              void* d_out, int out_size) {
    const float* node  = (const float*)d_in[0];
    const float* eemb  = (const float*)d_in[1];
    const int*   eidx  = (const int*)  d_in[2];
    const float* gamma = (const float*)d_in[3];
    const float* beta  = (const float*)d_in[4];
    const float* W1    = (const float*)d_in[5];
    const float* b1    = (const float*)d_in[6];
    const float* W2    = (const float*)d_in[7];
    const float* b2    = (const float*)d_in[8];
    const float* Wt    = (const float*)d_in[9];
    const float* bt    = (const float*)d_in[10];
    float* out = (float*)d_out;

    cudaFuncSetAttribute(edge_kernel, cudaFuncAttributeMaxDynamicSharedMemorySize,
                         EDGE_SMEM);
    cudaFuncSetAttribute(out_kernel, cudaFuncAttributeMaxDynamicSharedMemorySize,
                         OUT_SMEM);

    prep_kernel<<<128, 256>>>(W1, W2, Wt);
    ln_kernel<<<(N_NODES + 7) / 8, 256>>>(node, gamma, beta);
    edge_kernel<<<N_EDGES / TE, ETH, EDGE_SMEM>>>(eemb, eidx, b1, b2);
    out_kernel<<<(N_NODES + 127) / 128, 256, OUT_SMEM>>>(bt, out);
}

// round 9
// speedup vs baseline: 3.9937x; 1.0157x over previous
#include <cuda_runtime.h>
#include <cuda_fp16.h>
#include <cstdint>

#define N_NODES 50000
#define EMBED 128
#define HIDDEN 256
#define N_EDGES 640000
#define LN_EPS 1e-5f

// ---------------- warp MMA / cp.async helpers (sm_80-class) ----------------
__device__ __forceinline__ uint32_t smem_u32(const void* p) {
    uint32_t a;
    asm("{ .reg .u64 t; cvta.to.shared.u64 t, %1; cvt.u32.u64 %0, t; }"
        : "=r"(a) : "l"(p));
    return a;
}
__device__ __forceinline__ void mma_f16(float* d, const uint32_t* a, const uint32_t* b) {
    asm volatile(
        "mma.sync.aligned.m16n8k16.row.col.f32.f16.f16.f32 "
        "{%0,%1,%2,%3}, {%4,%5,%6,%7}, {%8,%9}, {%0,%1,%2,%3};"
        : "+f"(d[0]), "+f"(d[1]), "+f"(d[2]), "+f"(d[3])
        : "r"(a[0]), "r"(a[1]), "r"(a[2]), "r"(a[3]), "r"(b[0]), "r"(b[1]));
}
__device__ __forceinline__ void ldm4(uint32_t* r, uint32_t addr) {
    asm volatile("ldmatrix.sync.aligned.m8n8.x4.shared.b16 {%0,%1,%2,%3}, [%4];"
                 : "=r"(r[0]), "=r"(r[1]), "=r"(r[2]), "=r"(r[3]) : "r"(addr));
}
__device__ __forceinline__ void ldm2(uint32_t* r, uint32_t addr) {
    asm volatile("ldmatrix.sync.aligned.m8n8.x2.shared.b16 {%0,%1}, [%2];"
                 : "=r"(r[0]), "=r"(r[1]) : "r"(addr));
}
__device__ __forceinline__ void cpa16(uint32_t dst, const void* src) {
    asm volatile("cp.async.cg.shared.global [%0], [%1], 16;" :: "r"(dst), "l"(src));
}
#define CP_COMMIT() asm volatile("cp.async.commit_group;" ::: "memory")
#define CP_WAIT(n)  asm volatile("cp.async.wait_group %0;" :: "n"(n) : "memory")

__device__ __forceinline__ float silu_f(float x) {
    return __fdividef(x, 1.0f + __expf(-x));
}

// ---------------- device scratch ----------------
__device__ float g_h[N_NODES * EMBED];     // layernormed node embeddings
__device__ float g_agg[N_NODES * EMBED];   // init to h; edge atomics add msg -> h+agg
// fp16 transposed weight images: w1 [n=256][k=128], w2 [n=128][kk=256], wt [n=128][k=128]
__device__ __align__(16) __half g_w1h[32768];
__device__ __align__(16) __half g_w2h[32768];
__device__ __align__(16) __half g_wth[16384];

// ---------------------------------------------------------------------------
// Kernel 1 (fused): blocks 0..127 = weight prep; rest = LayerNorm (warp/row).
// ln writes h into BOTH g_h and g_agg (so edge atomics accumulate onto h).
// ---------------------------------------------------------------------------
#define PREP_BLOCKS 128

__global__ void init_kernel(const float* __restrict__ x,
                            const float* __restrict__ gamma,
                            const float* __restrict__ beta,
                            const float* __restrict__ W1,
                            const float* __restrict__ W2,
                            const float* __restrict__ Wt) {
    if (blockIdx.x < PREP_BLOCKS) {
        int idx = blockIdx.x * blockDim.x + threadIdx.x;   // 0..32767
        {   // W1 [k=128][n=256] -> [n][k]
            int k = idx >> 8, n = idx & 255;
            g_w1h[n * 128 + k] = __float2half_rn(W1[idx]);
        }
        {   // W2 [kk=256][n=128] -> [n][kk]
            int kk = idx >> 7, n = idx & 127;
            g_w2h[n * 256 + kk] = __float2half_rn(W2[idx]);
        }
        if (idx < 16384) {   // Wt [k=128][n=128] -> [n][k]
            int k = idx >> 7, n = idx & 127;
            g_wth[n * 128 + k] = __float2half_rn(Wt[idx]);
        }
        return;
    }

    int warp = ((blockIdx.x - PREP_BLOCKS) * blockDim.x + threadIdx.x) >> 5;
    int lane = threadIdx.x & 31;
    if (warp >= N_NODES) return;

    const float4* row = (const float4*)(x + (size_t)warp * EMBED);
    float4 v = row[lane];
    float s  = v.x + v.y + v.z + v.w;
    float ss = v.x * v.x + v.y * v.y + v.z * v.z + v.w * v.w;
    #pragma unroll
    for (int o = 16; o; o >>= 1) {
        s  += __shfl_xor_sync(0xFFFFFFFFu, s,  o);
        ss += __shfl_xor_sync(0xFFFFFFFFu, ss, o);
    }
    const float inv_d = 1.0f / (float)EMBED;
    float mu  = s * inv_d;
    float var = ss * inv_d - mu * mu;
    float inv = rsqrtf(var + LN_EPS);

    float4 g = ((const float4*)gamma)[lane];
    float4 b = ((const float4*)beta)[lane];
    float4 o4;
    o4.x = (v.x - mu) * inv * g.x + b.x;
    o4.y = (v.y - mu) * inv * g.y + b.y;
    o4.z = (v.z - mu) * inv * g.z + b.z;
    o4.w = (v.w - mu) * inv * g.w + b.w;
    ((float4*)(g_h + (size_t)warp * EMBED))[lane] = o4;
    ((float4*)(g_agg + (size_t)warp * EMBED))[lane] = o4;   // agg starts at h
}

// ---------------------------------------------------------------------------
// Kernel 2: fp16 mma.sync edge MLP. 128 edges/CTA, 8 warps, 2 CTAs/SM.
// (unchanged — at HMMA issue floor)
// ---------------------------------------------------------------------------
#define TE 128
#define ETH 256
#define A_STRIDE 264   // halves; 528B rows -> 16B-rotating, ldmatrix conflict-free
#define B_STRIDE 136   // halves; 272B rows

#define SM_CI   0
#define SM_NI   512
#define SM_B1   1024
#define SM_B2   2048
#define SM_A    2560
#define SM_B    (SM_A + 128 * A_STRIDE * 2)   // 70144
#define EDGE_SMEM (SM_B + 128 * B_STRIDE * 2) // 104960  -> 2 CTAs/SM

__device__ __forceinline__ void cp_tile(uint32_t sdst,
                                        const __half* __restrict__ src,
                                        int src_stride_halves, int tid) {
    #pragma unroll
    for (int i = tid; i < 2048; i += ETH) {
        int r = i >> 4, c = i & 15;
        cpa16(sdst + r * (B_STRIDE * 2) + c * 16,
              src + r * src_stride_halves + c * 8);
    }
}

__global__ __launch_bounds__(ETH, 2)
void edge_kernel(const float* __restrict__ eemb,
                 const int* __restrict__ eidx,
                 const float* __restrict__ b1g,
                 const float* __restrict__ b2g) {
    extern __shared__ char smem[];
    uint32_t sbase = smem_u32(smem);
    int tid = threadIdx.x, wid = tid >> 5, lane = tid & 31;
    int e0 = blockIdx.x * TE;

    int*   s_ci = (int*)(smem + SM_CI);
    int*   s_ni = (int*)(smem + SM_NI);
    float* sb1  = (float*)(smem + SM_B1);
    float* sb2  = (float*)(smem + SM_B2);

    cp_tile(sbase + SM_B, g_w1h, 128, tid); CP_COMMIT();

    if (tid < 128) {
        s_ci[tid] = eidx[e0 + tid];
        s_ni[tid] = eidx[N_EDGES + e0 + tid];
    }
    sb1[tid] = b1g[tid];
    if (tid < 128) sb2[tid] = b2g[tid];
    __syncthreads();

    #pragma unroll
    for (int it = 0; it < 16; it++) {
        int v = tid + ETH * it;
        int m = v >> 5, c = v & 31;
        float4 ee = ((const float4*)(eemb + (size_t)(e0 + m) * EMBED))[c];
        float4 hc = ((const float4*)(g_h + (size_t)s_ci[m] * EMBED))[c];
        float4 hn = ((const float4*)(g_h + (size_t)s_ni[m] * EMBED))[c];
        float s0 = silu_f(ee.x + hc.x + hn.x);
        float s1 = silu_f(ee.y + hc.y + hn.y);
        float s2 = silu_f(ee.z + hc.z + hn.z);
        float s3 = silu_f(ee.w + hc.w + hn.w);
        __half2 p0 = __floats2half2_rn(s0, s1);
        __half2 p1 = __floats2half2_rn(s2, s3);
        int off = (m * A_STRIDE + 4 * c) * 2;
        *(__half2*)(smem + SM_A + off)     = p0;
        *(__half2*)(smem + SM_A + off + 4) = p1;
    }

    int rb = wid * 16;
    int ai = lane & 7, as_ = lane >> 3;
    int arow = rb + ai + (as_ & 1) * 8;
    int acolseg = (as_ >> 1) * 8;
    int bi = lane & 7, bs = (lane >> 3) & 1;
    int q = lane & 3;
    int r0 = rb + (lane >> 2), r1 = r0 + 8;

    // ================= GEMM1 (two n-halves) =================
    #pragma unroll 1
    for (int h = 0; h < 2; h++) {
        CP_WAIT(0);
        __syncthreads();

        float acc[16][4];
        #pragma unroll
        for (int i = 0; i < 16; i++)
            #pragma unroll
            for (int j = 0; j < 4; j++) acc[i][j] = 0.f;

        #pragma unroll
        for (int ks = 0; ks < 8; ks++) {
            uint32_t a4[4];
            uint32_t aoff = (uint32_t)(arow * A_STRIDE + ks * 16 + acolseg) * 2;
            ldm4(a4, sbase + SM_A + aoff);
            #pragma unroll
            for (int nt = 0; nt < 16; nt++) {
                uint32_t boff = (uint32_t)((nt * 8 + bi) * B_STRIDE + ks * 16 + bs * 8) * 2;
                uint32_t bw[2];
                ldm2(bw, sbase + SM_B + boff);
                mma_f16(acc[nt], a4, bw);
            }
        }
        __syncthreads();

        if (h == 0) { cp_tile(sbase + SM_B, g_w1h + 16384, 128, tid); CP_COMMIT(); }
        else        { cp_tile(sbase + SM_B, g_w2h,         256, tid); CP_COMMIT(); }

        int dbase = (h == 0) ? 128 : 0;
        #pragma unroll
        for (int nt = 0; nt < 16; nt++) {
            int c0 = nt * 8 + 2 * q;
            int gc = h * 128 + c0;
            float t0 = silu_f(acc[nt][0] + sb1[gc]);
            float t1 = silu_f(acc[nt][1] + sb1[gc + 1]);
            float t2 = silu_f(acc[nt][2] + sb1[gc]);
            float t3 = silu_f(acc[nt][3] + sb1[gc + 1]);
            int o0 = (r0 * A_STRIDE + dbase + c0) * 2;
            int o1 = (r1 * A_STRIDE + dbase + c0) * 2;
            *(__half2*)(smem + SM_A + o0) = __floats2half2_rn(t0, t1);
            *(__half2*)(smem + SM_A + o1) = __floats2half2_rn(t2, t3);
        }
    }

    // ================= GEMM2 (two k-phases) =============
    float acc2[16][4];
    #pragma unroll
    for (int i = 0; i < 16; i++)
        #pragma unroll
        for (int j = 0; j < 4; j++) acc2[i][j] = 0.f;

    #pragma unroll 1
    for (int ph = 0; ph < 2; ph++) {
        CP_WAIT(0);
        __syncthreads();

        int abase = (ph == 0) ? 128 : 0;
        #pragma unroll
        for (int ks = 0; ks < 8; ks++) {
            uint32_t a4[4];
            uint32_t aoff = (uint32_t)(arow * A_STRIDE + abase + ks * 16 + acolseg) * 2;
            ldm4(a4, sbase + SM_A + aoff);
            #pragma unroll
            for (int nt = 0; nt < 16; nt++) {
                uint32_t boff = (uint32_t)((nt * 8 + bi) * B_STRIDE + ks * 16 + bs * 8) * 2;
                uint32_t bw[2];
                ldm2(bw, sbase + SM_B + boff);
                mma_f16(acc2[nt], a4, bw);
            }
        }
        if (ph == 0) {
            __syncthreads();
            cp_tile(sbase + SM_B, g_w2h + 128, 256, tid); CP_COMMIT();
        }
    }

    // ---- epilogue ----
    {
        int ci0 = s_ci[r0], ci1 = s_ci[r1];
        int ni0 = s_ni[r0], ni1 = s_ni[r1];
        const float* hn0 = g_h + (size_t)ni0 * EMBED;
        const float* hn1 = g_h + (size_t)ni1 * EMBED;
        float* ag0 = g_agg + (size_t)ci0 * EMBED;
        float* ag1 = g_agg + (size_t)ci1 * EMBED;
        #pragma unroll
        for (int nt = 0; nt < 16; nt++) {
            int c0 = nt * 8 + 2 * q;
            float2 h0 = *(const float2*)(hn0 + c0);
            float2 h1 = *(const float2*)(hn1 + c0);
            atomicAdd(ag0 + c0,     (acc2[nt][0] + sb2[c0])     * h0.x);
            atomicAdd(ag0 + c0 + 1, (acc2[nt][1] + sb2[c0 + 1]) * h0.y);
            atomicAdd(ag1 + c0,     (acc2[nt][2] + sb2[c0])     * h1.x);
            atomicAdd(ag1 + c0 + 1, (acc2[nt][3] + sb2[c0 + 1]) * h1.y);
        }
    }
}

// ---------------------------------------------------------------------------
// Kernel 3: out = silu(g_agg) @ Wt + bt  (g_agg already holds h + agg)
// 64 node rows/CTA, 256 threads, 3 CTAs/SM; warps 0-3 do the MMA.
// ---------------------------------------------------------------------------
#define ONR 64
#define OSM_BT  0
#define OSM_A   512
#define OSM_B   (OSM_A + ONR * B_STRIDE * 2)    // 17920
#define OUT_SMEM (OSM_B + 128 * B_STRIDE * 2)   // 52736

__global__ __launch_bounds__(256, 3)
void out_kernel(const float* __restrict__ btg, float* __restrict__ out) {
    extern __shared__ char smem[];
    uint32_t sbase = smem_u32(smem);
    int tid = threadIdx.x, wid = tid >> 5, lane = tid & 31;
    int n0 = blockIdx.x * ONR;

    float* sbt = (float*)(smem + OSM_BT);

    // prefetch Wt^T tile (overlaps gather)
    cp_tile(sbase + OSM_B, g_wth, 128, tid); CP_COMMIT();
    if (tid < 128) sbt[tid] = btg[tid];

    // ---- gather: A = fp16(silu(agg)) [64 rows x 128 cols], 8 iters ----
    #pragma unroll
    for (int it = 0; it < 8; it++) {
        int v = tid + 256 * it;       // 0..2047
        int m = v >> 5, c = v & 31;
        int row = n0 + m;
        float s0 = 0.f, s1 = 0.f, s2 = 0.f, s3 = 0.f;
        if (row < N_NODES) {
            float4 av = ((const float4*)(g_agg + (size_t)row * EMBED))[c];
            s0 = silu_f(av.x);
            s1 = silu_f(av.y);
            s2 = silu_f(av.z);
            s3 = silu_f(av.w);
        }
        int off = (m * B_STRIDE + 4 * c) * 2;
        *(__half2*)(smem + OSM_A + off)     = __floats2half2_rn(s0, s1);
        *(__half2*)(smem + OSM_A + off + 4) = __floats2half2_rn(s2, s3);
    }

    CP_WAIT(0);
    __syncthreads();

    if (wid < 4) {
        int rb = wid * 16;
        int ai = lane & 7, as_ = lane >> 3;
        int arow = rb + ai + (as_ & 1) * 8;
        int acolseg = (as_ >> 1) * 8;
        int bi = lane & 7, bs = (lane >> 3) & 1;
        int q = lane & 3;
        int r0 = rb + (lane >> 2), r1 = r0 + 8;

        float acc[16][4];
        #pragma unroll
        for (int i = 0; i < 16; i++)
            #pragma unroll
            for (int j = 0; j < 4; j++) acc[i][j] = 0.f;

        #pragma unroll
        for (int ks = 0; ks < 8; ks++) {
            uint32_t a4[4];
            uint32_t aoff = (uint32_t)(arow * B_STRIDE + ks * 16 + acolseg) * 2;
            ldm4(a4, sbase + OSM_A + aoff);
            #pragma unroll
            for (int nt = 0; nt < 16; nt++) {
                uint32_t boff = (uint32_t)((nt * 8 + bi) * B_STRIDE + ks * 16 + bs * 8) * 2;
                uint32_t bw[2];
                ldm2(bw, sbase + OSM_B + boff);
                mma_f16(acc[nt], a4, bw);
            }
        }

        // ---- epilogue: out[row][c] = acc + bt[c] ----
        int row0 = n0 + r0, row1 = n0 + r1;
        #pragma unroll
        for (int nt = 0; nt < 16; nt++) {
            int c0 = nt * 8 + 2 * q;
            float2 b2 = *(const float2*)(sbt + c0);
            if (row0 < N_NODES) {
                float2 o0 = make_float2(acc[nt][0] + b2.x, acc[nt][1] + b2.y);
                *(float2*)(out + (size_t)row0 * EMBED + c0) = o0;
            }
            if (row1 < N_NODES) {
                float2 o1 = make_float2(acc[nt][2] + b2.x, acc[nt][3] + b2.y);
                *(float2*)(out + (size_t)row1 * EMBED + c0) = o1;
            }
        }
    }
}

// ---------------------------------------------------------------------------
extern "C" void kernel_launch(void* const* d_in, const int* in_sizes, int n_in,
                              void* d_out, int out_size) {
    const float* node  = (const float*)d_in[0];
    const float* eemb  = (const float*)d_in[1];
    const int*   eidx  = (const int*)  d_in[2];
    const float* gamma = (const float*)d_in[3];
    const float* beta  = (const float*)d_in[4];
    const float* W1    = (const float*)d_in[5];
    const float* b1    = (const float*)d_in[6];
    const float* W2    = (const float*)d_in[7];
    const float* b2    = (const float*)d_in[8];
    const float* Wt    = (const float*)d_in[9];
    const float* bt    = (const float*)d_in[10];
    float* out = (float*)d_out;

    cudaFuncSetAttribute(edge_kernel, cudaFuncAttributeMaxDynamicSharedMemorySize,
                         EDGE_SMEM);
    cudaFuncSetAttribute(out_kernel, cudaFuncAttributeMaxDynamicSharedMemorySize,
                         OUT_SMEM);

    init_kernel<<<PREP_BLOCKS + (N_NODES + 7) / 8, 256>>>(node, gamma, beta, W1, W2, Wt);
    edge_kernel<<<N_EDGES / TE, ETH, EDGE_SMEM>>>(eemb, eidx, b1, b2);
    out_kernel<<<(N_NODES + ONR - 1) / ONR, 256, OUT_SMEM>>>(bt, out);
}